// round 10
// baseline (speedup 1.0000x reference)
#include <cuda_runtime.h>
#include <math.h>

#define S3 262144        // 64^3
#define NMODE 6912       // 4 corners * 1728

// ---------------- scratch ----------------
__device__ float  g_v[64*S3];
__device__ float  g_s[64*S3];
__device__ float2 g_B[64*64*288];
__device__ float2 g_X[64*NMODE];   // corner-major: c*NMODE + corner*1728 + cmode
__device__ float2 g_Y[64*NMODE];
__device__ float  g_h1[1024];
__device__ float  g_film[384];
__device__ double g_gn[16];
__device__ float  g_gnf[16];
__device__ __align__(16) float2 tw_fWt[64*12];   // [w][kw]  fwd W twiddle, transposed
__device__ __align__(16) float2 tw_iW[12*64];    // [kw][w]  inv W twiddle * alpha/64^3
__device__ __align__(16) float2 tw_fDHt[64*24];  // [x][j]   fwd D/H twiddle, transposed
__device__ __align__(16) float2 tw_iDH[24*64];   // [j][x]   inv D/H twiddle
__device__ float4 tw_fW4[64*12];   // [w][kw]   (c, c, -s, -s)   fwd W dup
__device__ float4 tw_fDH8[64*12];  // [h][jp]   (c0, c1, -s0, -s1) fwd D/H jh-pairs

__device__ __forceinline__ float gelu_f(float x){
    return 0.5f*x*(1.0f + erff(x*0.7071067811865476f));
}

#define CMAC(acc, a, t) { acc.x += a.x*t.x - a.y*t.y; acc.y += a.x*t.y + a.y*t.x; }

// ---------------- packed f32x2 helpers ----------------
__device__ __forceinline__ unsigned long long ffma2(unsigned long long a, unsigned long long b, unsigned long long c){
    unsigned long long d;
    asm("fma.rn.f32x2 %0, %1, %2, %3;" : "=l"(d) : "l"(a), "l"(b), "l"(c));
    return d;
}
__device__ __forceinline__ unsigned long long pk(float lo, float hi){
    unsigned long long r; asm("mov.b64 %0, {%1, %2};" : "=l"(r) : "f"(lo), "f"(hi)); return r;
}
__device__ __forceinline__ float2 upk(unsigned long long v){
    float2 r; asm("mov.b64 {%0, %1}, %2;" : "=f"(r.x), "=f"(r.y) : "l"(v)); return r;
}

// ---------------- tables ----------------
__global__ void init_tables_k(){
    int t = blockIdx.x*blockDim.x + threadIdx.x;
    const double w0 = 6.283185307179586476925286766559/64.0;
    if(t < 768){
        int kw = t>>6, w = t&63;
        double s,c; sincos(w0*(double)(kw*w), &s, &c);
        tw_fWt[w*12+kw] = make_float2((float)c, (float)(-s));
        tw_fW4[w*12+kw] = make_float4((float)c, (float)c, (float)(-s), (float)(-s));
        double al = (kw==0 ? 1.0 : 2.0) / 262144.0;
        tw_iW[kw*64+w] = make_float2((float)(al*c), (float)(al*s));
    }
    if(t < 1536){
        int j = t>>6, x = t&63;
        int bin = (j<12) ? j : (j+40);
        double s,c; sincos(w0*(double)(bin*x), &s, &c);
        tw_fDHt[x*24+j] = make_float2((float)c, (float)(-s));
        tw_iDH[j*64+x]  = make_float2((float)c, (float)( s));
    }
    if(t < 768){
        int h = t/12, jp = t - (t/12)*12;
        int j0 = 2*jp, j1 = 2*jp+1;
        int b0 = (j0<12)? j0 : j0+40;
        int b1 = (j1<12)? j1 : j1+40;
        double s0,c0,s1,c1;
        sincos(w0*(double)(b0*h), &s0, &c0);
        sincos(w0*(double)(b1*h), &s1, &c1);
        tw_fDH8[t] = make_float4((float)c0, (float)c1, (float)(-s0), (float)(-s1));
    }
    if(t < 16) g_gn[t] = 0.0;
}

// ---------------- FiLM ----------------
__global__ void film1_k(const float* __restrict__ latent, const float* __restrict__ w,
                        const float* __restrict__ b){
    int wid  = (blockIdx.x*blockDim.x + threadIdx.x) >> 5;
    int lane = threadIdx.x & 31;
    if(wid >= 1024) return;
    const float* wr = w + wid*512;
    float acc = 0.f;
    for(int k=lane;k<512;k+=32) acc += latent[k]*wr[k];
    #pragma unroll
    for(int o=16;o;o>>=1) acc += __shfl_xor_sync(0xffffffffu, acc, o);
    if(lane==0) g_h1[wid] = gelu_f(acc + b[wid]);
}
__global__ void film2_k(const float* __restrict__ w, const float* __restrict__ b){
    int wid  = (blockIdx.x*blockDim.x + threadIdx.x) >> 5;
    int lane = threadIdx.x & 31;
    if(wid >= 384) return;
    const float* wr = w + wid*1024;
    float acc = 0.f;
    for(int k=lane;k<1024;k+=32) acc += g_h1[k]*wr[k];
    #pragma unroll
    for(int o=16;o;o>>=1) acc += __shfl_xor_sync(0xffffffffu, acc, o);
    if(lane==0) g_film[wid] = acc + b[wid];
}

// ---------------- lift + conv(layer0), f32x2 packed ----------------
__global__ void __launch_bounds__(256) lift_conv_k(const float* __restrict__ x,
        const float* __restrict__ lw, const float* __restrict__ lb,
        const float* __restrict__ cw, const float* __restrict__ cb){
    int s0 = blockIdx.x*128;
    __shared__ float vsh[64][128];
    __shared__ float2 wsh2[64][66];
    int s = threadIdx.x & 127, chalf = threadIdx.x >> 7;
    float x0 = __ldg(&x[s0+s]),        x1 = __ldg(&x[S3+s0+s]);
    float x2 = __ldg(&x[2*S3+s0+s]),   x3 = __ldg(&x[3*S3+s0+s]);
    for(int i=threadIdx.x;i<4096;i+=256){ float wv = cw[i]; wsh2[i&63][i>>6] = make_float2(wv, wv); }
    #pragma unroll
    for(int i=0;i<32;i++){
        int cc = i*2 + chalf;
        float v = __ldg(&lb[cc]) + __ldg(&lw[cc*4+0])*x0 + __ldg(&lw[cc*4+1])*x1
                                 + __ldg(&lw[cc*4+2])*x2 + __ldg(&lw[cc*4+3])*x3;
        vsh[cc][s] = v;
        g_v[(size_t)cc*S3 + s0 + s] = v;
    }
    __syncthreads();
    int o0 = (threadIdx.x>>5)*8, si = (threadIdx.x&31)*4;
    unsigned long long a01[8], a23[8];
    #pragma unroll
    for(int a=0;a<8;a++){ a01[a]=0ull; a23[a]=0ull; }
    for(int k=0;k<64;k++){
        ulonglong2 v = *(const ulonglong2*)&vsh[k][si];
        const ulonglong2* wp = (const ulonglong2*)&wsh2[k][o0];
        ulonglong2 wA = wp[0], wB = wp[1], wC = wp[2], wD = wp[3];
        a01[0]=ffma2(wA.x,v.x,a01[0]); a23[0]=ffma2(wA.x,v.y,a23[0]);
        a01[1]=ffma2(wA.y,v.x,a01[1]); a23[1]=ffma2(wA.y,v.y,a23[1]);
        a01[2]=ffma2(wB.x,v.x,a01[2]); a23[2]=ffma2(wB.x,v.y,a23[2]);
        a01[3]=ffma2(wB.y,v.x,a01[3]); a23[3]=ffma2(wB.y,v.y,a23[3]);
        a01[4]=ffma2(wC.x,v.x,a01[4]); a23[4]=ffma2(wC.x,v.y,a23[4]);
        a01[5]=ffma2(wC.y,v.x,a01[5]); a23[5]=ffma2(wC.y,v.y,a23[5]);
        a01[6]=ffma2(wD.x,v.x,a01[6]); a23[6]=ffma2(wD.x,v.y,a23[6]);
        a01[7]=ffma2(wD.y,v.x,a01[7]); a23[7]=ffma2(wD.y,v.y,a23[7]);
    }
    #pragma unroll
    for(int oi=0;oi<8;oi++){
        float bb = __ldg(&cb[o0+oi]);
        float2 lo = upk(a01[oi]), hi = upk(a23[oi]);
        *(float4*)&g_s[(size_t)(o0+oi)*S3 + s0 + si] =
            make_float4(lo.x+bb, lo.y+bb, hi.x+bb, hi.y+bb);
    }
}

// ---------------- fused forward DFT: W then H, f32x2 packed ----------------
__global__ void __launch_bounds__(128) fwdWH_k(){
    int d0 = blockIdx.x*2, c = blockIdx.y;
    __shared__ float  vsh[2][64][65];
    __shared__ float2 AshC[2][12][66];
    for(int i=threadIdx.x;i<2048;i+=128){
        int p = i>>10, j = i&1023;
        float4 v4 = *(const float4*)(g_v + (size_t)(c*64+d0+p)*4096 + j*4);
        int h = j>>4, w4 = (j&15)*4;
        vsh[p][h][w4]=v4.x; vsh[p][h][w4+1]=v4.y; vsh[p][h][w4+2]=v4.z; vsh[p][h][w4+3]=v4.w;
    }
    __syncthreads();
    int p = threadIdx.x>>6, t6 = threadIdx.x&63;
    {
        int hp = t6&31, kw0 = (t6>>5)*6;
        unsigned long long aRe[6], aIm[6];
        #pragma unroll
        for(int j=0;j<6;j++){ aRe[j]=0ull; aIm[j]=0ull; }
        for(int w=0;w<64;w++){
            unsigned long long v2 = pk(vsh[p][2*hp][w], vsh[p][2*hp+1][w]);
            #pragma unroll
            for(int j=0;j<6;j++){
                ulonglong2 tt = *(const ulonglong2*)&tw_fW4[w*12+kw0+j];
                aRe[j] = ffma2(v2, tt.x, aRe[j]);
                aIm[j] = ffma2(v2, tt.y, aIm[j]);
            }
        }
        #pragma unroll
        for(int j=0;j<6;j++){
            float2 r = upk(aRe[j]), q = upk(aIm[j]);
            AshC[p][kw0+j][2*hp]   = make_float2(r.x, q.x);
            AshC[p][kw0+j][2*hp+1] = make_float2(r.y, q.y);
        }
    }
    __syncthreads();
    if(t6 < 48){
        int kw = t6 % 12, jq = t6 / 12;
        unsigned long long oRe[3], oIm[3];
        #pragma unroll
        for(int r=0;r<3;r++){ oRe[r]=0ull; oIm[r]=0ull; }
        for(int h=0;h<64;h++){
            float2 a = AshC[p][kw][h];
            unsigned long long aR  = pk(a.x,  a.x);
            unsigned long long aI  = pk(a.y,  a.y);
            unsigned long long aIn = pk(-a.y, -a.y);
            #pragma unroll
            for(int r=0;r<3;r++){
                ulonglong2 T = *(const ulonglong2*)&tw_fDH8[h*12 + jq*3 + r];
                oRe[r] = ffma2(aR,  T.x, oRe[r]);
                oRe[r] = ffma2(aIn, T.y, oRe[r]);
                oIm[r] = ffma2(aR,  T.y, oIm[r]);
                oIm[r] = ffma2(aI,  T.x, oIm[r]);
            }
        }
        float2* dst = g_B + (size_t)(c*64+d0+p)*288;
        #pragma unroll
        for(int r=0;r<3;r++){
            int jp = jq*3+r;
            float2 re2 = upk(oRe[r]), im2 = upk(oIm[r]);
            dst[(2*jp)*12+kw]   = make_float2(re2.x, im2.x);
            dst[(2*jp+1)*12+kw] = make_float2(re2.y, im2.y);
        }
    }
}

// ---------------- forward DFT over D (stores corner-major) ----------------
__global__ void __launch_bounds__(128) fwdD_k(){
    int jh = blockIdx.x, c = blockIdx.y;
    __shared__ float2 Bsh[64][12];
    for(int i=threadIdx.x;i<768;i+=128){
        int d = i/12, kw = i - d*12;
        Bsh[d][kw] = g_B[(size_t)(c*64+d)*288 + jh*12 + kw];
    }
    __syncthreads();
    if(threadIdx.x < 96){
        int kw = threadIdx.x % 12, jd0 = (threadIdx.x/12)*3;
        float2 b0={0,0},b1={0,0},b2={0,0};
        for(int d=0;d<64;d++){
            float2 a = Bsh[d][kw];
            float2 t0 = __ldg(&tw_fDHt[d*24+jd0]);
            float2 t1 = __ldg(&tw_fDHt[d*24+jd0+1]);
            float2 t2 = __ldg(&tw_fDHt[d*24+jd0+2]);
            CMAC(b0,a,t0); CMAC(b1,a,t1); CMAC(b2,a,t2);
        }
        int jhm = jh % 12, cbase = (jh>=12) ? 2 : 0;
        #pragma unroll
        for(int r=0;r<3;r++){
            int jd = jd0 + r;
            int corner = cbase + (jd>=12 ? 1 : 0);
            int cmode = ((jd%12)*12 + jhm)*12 + kw;
            float2 b = (r==0)?b0:(r==1)?b1:b2;
            g_X[(size_t)c*NMODE + corner*1728 + cmode] = b;
        }
    }
}

// ---------------- per-mode channel mix: float4 streaming ----------------
__global__ void __launch_bounds__(256) mix_k(const float* __restrict__ w1, const float* __restrict__ w2,
                                             const float* __restrict__ w3, const float* __restrict__ w4){
    int corner = blockIdx.x / 27;
    int c0 = (blockIdx.x - corner*27) * 64;
    const float* wbase = (corner==0)?w1:(corner==1)?w2:(corner==2)?w3:w4;
    __shared__ float2 xs[64][64];
    int tx = threadIdx.x & 31, ty = threadIdx.x >> 5;
    for(int i=ty; i<64; i+=8)
        ((float4*)xs[i])[tx] = *(const float4*)(&g_X[(size_t)i*NMODE + corner*1728 + c0 + tx*2]);
    __syncthreads();
    int o = blockIdx.y*8 + ty;
    const float* Wp = wbase + ((size_t)o*1728 + c0 + tx*2)*2;
    float re0=0.f,im0=0.f,re1=0.f,im1=0.f;
    #pragma unroll 8
    for(int i=0;i<64;i++){
        float4 wv = *(const float4*)(Wp + (size_t)i*221184);
        float4 xx = ((const float4*)xs[i])[tx];
        re0 += xx.x*wv.x - xx.y*wv.y; im0 += xx.x*wv.y + xx.y*wv.x;
        re1 += xx.z*wv.z - xx.w*wv.w; im1 += xx.z*wv.w + xx.w*wv.z;
    }
    *(float4*)(&g_Y[(size_t)o*NMODE + corner*1728 + c0 + tx*2]) = make_float4(re0,im0,re1,im1);
}

// ---------------- inverse DFT over D (reads corner-major) ----------------
__global__ void __launch_bounds__(128) invD_k(){
    int jh = blockIdx.x, c = blockIdx.y;
    __shared__ __align__(16) float2 Ysh[24][12];
    int jhm = jh % 12, cbase = (jh>=12) ? 2 : 0;
    for(int i=threadIdx.x;i<288;i+=128){
        int jd = i/12, kw = i - jd*12;
        int corner = cbase + (jd>=12 ? 1 : 0);
        int cmode = ((jd%12)*12 + jhm)*12 + kw;
        Ysh[jd][kw] = g_Y[(size_t)c*NMODE + corner*1728 + cmode];
    }
    __syncthreads();
    int d = threadIdx.x & 63, kw0 = (threadIdx.x>>6)*6;
    float2 a0={0,0},a1={0,0},a2={0,0},a3={0,0},a4={0,0},a5={0,0};
    for(int jd=0;jd<24;jd++){
        float2 t = __ldg(&tw_iDH[jd*64+d]);
        const float4* yp = (const float4*)(&Ysh[jd][kw0]);
        float4 y0 = yp[0], y1 = yp[1], y2 = yp[2];
        float2 v;
        v = make_float2(y0.x,y0.y); CMAC(a0,v,t);
        v = make_float2(y0.z,y0.w); CMAC(a1,v,t);
        v = make_float2(y1.x,y1.y); CMAC(a2,v,t);
        v = make_float2(y1.z,y1.w); CMAC(a3,v,t);
        v = make_float2(y2.x,y2.y); CMAC(a4,v,t);
        v = make_float2(y2.z,y2.w); CMAC(a5,v,t);
    }
    float2* dst = g_B + (size_t)(c*64+d)*288 + jh*12 + kw0;
    dst[0]=a0; dst[1]=a1; dst[2]=a2; dst[3]=a3; dst[4]=a4; dst[5]=a5;
}

// ---------------- fused inverse H + W + residual add + GN stats ----------------
__global__ void __launch_bounds__(128) invHW_gn_k(){
    int d = blockIdx.x, c = blockIdx.y;
    __shared__ __align__(16) float2 Bsh[288];
    __shared__ float2 Ash[12][64];
    __shared__ float redS[4], redQ[4];
    const float2* src = g_B + (size_t)(c*64+d)*288;
    for(int i=threadIdx.x;i<288;i+=128)  Bsh[i] = src[i];
    __syncthreads();
    {
        int h = threadIdx.x & 63, kw0 = (threadIdx.x>>6)*6;
        float2 a0={0,0},a1={0,0},a2={0,0},a3={0,0},a4={0,0},a5={0,0};
        for(int jh=0;jh<24;jh++){
            float2 t = __ldg(&tw_iDH[jh*64+h]);
            const float4* bp = (const float4*)(&Bsh[jh*12+kw0]);
            float4 b0 = bp[0], b1 = bp[1], b2 = bp[2];
            float2 v;
            v = make_float2(b0.x,b0.y); CMAC(a0,v,t);
            v = make_float2(b0.z,b0.w); CMAC(a1,v,t);
            v = make_float2(b1.x,b1.y); CMAC(a2,v,t);
            v = make_float2(b1.z,b1.w); CMAC(a3,v,t);
            v = make_float2(b2.x,b2.y); CMAC(a4,v,t);
            v = make_float2(b2.z,b2.w); CMAC(a5,v,t);
        }
        Ash[kw0+0][h]=a0; Ash[kw0+1][h]=a1; Ash[kw0+2][h]=a2;
        Ash[kw0+3][h]=a3; Ash[kw0+4][h]=a4; Ash[kw0+5][h]=a5;
    }
    __syncthreads();
    int wp = threadIdx.x & 31, hg = threadIdx.x >> 5;
    float2 tA[12], tB[12];
    #pragma unroll
    for(int kw=0;kw<12;kw++){ tA[kw]=__ldg(&tw_iW[kw*64+wp*2]); tB[kw]=__ldg(&tw_iW[kw*64+wp*2+1]); }
    float ssum=0.f, sq=0.f;
    float2* srow = (float2*)(g_s + (size_t)c*S3 + d*4096);
    for(int h=hg*16; h<hg*16+16; h++){
        float r0=0.f, r1=0.f;
        #pragma unroll
        for(int kw=0;kw<12;kw++){
            float2 a = Ash[kw][h];
            r0 += a.x*tA[kw].x - a.y*tA[kw].y;
            r1 += a.x*tB[kw].x - a.y*tB[kw].y;
        }
        float2 sv = srow[h*32+wp];
        sv.x += r0; sv.y += r1;
        srow[h*32+wp] = sv;
        ssum += sv.x + sv.y; sq += sv.x*sv.x + sv.y*sv.y;
    }
    #pragma unroll
    for(int o=16;o;o>>=1){ ssum += __shfl_xor_sync(0xffffffffu,ssum,o);
                           sq   += __shfl_xor_sync(0xffffffffu,sq,o); }
    if(wp==0){ redS[hg]=ssum; redQ[hg]=sq; }
    __syncthreads();
    if(threadIdx.x==0){
        float S = redS[0]+redS[1]+redS[2]+redS[3];
        float Q = redQ[0]+redQ[1]+redQ[2]+redQ[3];
        int g = c>>3;
        atomicAdd(&g_gn[g*2],   (double)S);
        atomicAdd(&g_gn[g*2+1], (double)Q);
    }
}

__global__ void gn_final_k(){
    int g = threadIdx.x;
    float mu_f=0.f, rs_f=0.f;
    if(g<8){
        double n = 8.0*(double)S3;
        double mu = g_gn[g*2]/n;
        double var = g_gn[g*2+1]/n - mu*mu;
        mu_f = (float)mu; rs_f = (float)(1.0/sqrt(var + 1e-5));
    }
    __syncthreads();
    if(g<8){ g_gnf[g*2]=mu_f; g_gnf[g*2+1]=rs_f; }
    if(g<16) g_gn[g]=0.0;
}

// ---------------- GN-apply + GELU + FiLM + conv(next layer), f32x2 packed ----------------
__global__ void __launch_bounds__(256) gn_apply_conv_k(const float* __restrict__ gg, const float* __restrict__ gb,
        int l, const float* __restrict__ cw, const float* __restrict__ cb){
    int s0 = blockIdx.x*128;
    __shared__ float vsh[64][128];
    __shared__ float2 wsh2[64][66];
    int s = threadIdx.x & 127, chalf = threadIdx.x >> 7;
    for(int i=threadIdx.x;i<4096;i+=256){ float wv = cw[i]; wsh2[i&63][i>>6] = make_float2(wv, wv); }
    #pragma unroll
    for(int i=0;i<32;i++){
        int cc = i*2 + chalf;
        int g = cc>>3;
        float xv = (g_s[(size_t)cc*S3+s0+s]-g_gnf[g*2])*g_gnf[g*2+1]*__ldg(&gg[cc]) + __ldg(&gb[cc]);
        float y = gelu_f(xv);
        float v = y*(1.f+g_film[(l*64+cc)*2]) + g_film[(l*64+cc)*2+1];
        vsh[cc][s] = v;
        g_v[(size_t)cc*S3+s0+s] = v;
    }
    __syncthreads();
    int o0 = (threadIdx.x>>5)*8, si = (threadIdx.x&31)*4;
    unsigned long long a01[8], a23[8];
    #pragma unroll
    for(int a=0;a<8;a++){ a01[a]=0ull; a23[a]=0ull; }
    for(int k=0;k<64;k++){
        ulonglong2 v = *(const ulonglong2*)&vsh[k][si];
        const ulonglong2* wp = (const ulonglong2*)&wsh2[k][o0];
        ulonglong2 wA = wp[0], wB = wp[1], wC = wp[2], wD = wp[3];
        a01[0]=ffma2(wA.x,v.x,a01[0]); a23[0]=ffma2(wA.x,v.y,a23[0]);
        a01[1]=ffma2(wA.y,v.x,a01[1]); a23[1]=ffma2(wA.y,v.y,a23[1]);
        a01[2]=ffma2(wB.x,v.x,a01[2]); a23[2]=ffma2(wB.x,v.y,a23[2]);
        a01[3]=ffma2(wB.y,v.x,a01[3]); a23[3]=ffma2(wB.y,v.y,a23[3]);
        a01[4]=ffma2(wC.x,v.x,a01[4]); a23[4]=ffma2(wC.x,v.y,a23[4]);
        a01[5]=ffma2(wC.y,v.x,a01[5]); a23[5]=ffma2(wC.y,v.y,a23[5]);
        a01[6]=ffma2(wD.x,v.x,a01[6]); a23[6]=ffma2(wD.x,v.y,a23[6]);
        a01[7]=ffma2(wD.y,v.x,a01[7]); a23[7]=ffma2(wD.y,v.y,a23[7]);
    }
    #pragma unroll
    for(int oi=0;oi<8;oi++){
        float bb = __ldg(&cb[o0+oi]);
        float2 lo = upk(a01[oi]), hi = upk(a23[oi]);
        *(float4*)&g_s[(size_t)(o0+oi)*S3 + s0 + si] =
            make_float4(lo.x+bb, lo.y+bb, hi.x+bb, hi.y+bb);
    }
}

// ---------------- last layer: GN-apply + FiLM + p1 + GELU + p2, f32x2 packed ----------------
__global__ void __launch_bounds__(256) gn_apply_head_k(const float* __restrict__ gg, const float* __restrict__ gb,
        int l, const float* __restrict__ w1, const float* __restrict__ b1,
        const float* __restrict__ w2, const float* __restrict__ b2, float* __restrict__ out){
    int s0 = blockIdx.x*64;
    __shared__ float vsh[64][64];
    __shared__ float2 wsh2[64][66];
    __shared__ float w2s[3][128];
    __shared__ float red[16][3][64];
    int s = threadIdx.x & 63, cq = threadIdx.x >> 6;
    for(int i=threadIdx.x;i<384;i+=256){ int j=i>>7, o=i&127; w2s[j][o]=w2[j*128+o]; }
    #pragma unroll
    for(int i=0;i<16;i++){
        int cc = i*4 + cq;
        int g = cc>>3;
        float xv = (g_s[(size_t)cc*S3+s0+s]-g_gnf[g*2])*g_gnf[g*2+1]*__ldg(&gg[cc]) + __ldg(&gb[cc]);
        float y = gelu_f(xv);
        vsh[cc][s] = y*(1.f+g_film[(l*64+cc)*2]) + g_film[(l*64+cc)*2+1];
    }
    int og = threadIdx.x >> 4, sg = threadIdx.x & 15;
    int o0 = og*4, si = sg*4;
    float p[3][4];
    #pragma unroll
    for(int j=0;j<3;j++){ p[j][0]=0.f;p[j][1]=0.f;p[j][2]=0.f;p[j][3]=0.f; }
    for(int half=0; half<2; half++){
        __syncthreads();
        for(int i=threadIdx.x;i<4096;i+=256){
            int o=i>>6,k=i&63; float wv = w1[(half*64+o)*64+k];
            wsh2[k][o] = make_float2(wv, wv);
        }
        __syncthreads();
        unsigned long long a01[4], a23[4];
        #pragma unroll
        for(int a=0;a<4;a++){ a01[a]=0ull; a23[a]=0ull; }
        for(int k=0;k<64;k++){
            ulonglong2 v = *(const ulonglong2*)&vsh[k][si];
            const ulonglong2* wp = (const ulonglong2*)&wsh2[k][o0];
            ulonglong2 wA = wp[0], wB = wp[1];
            a01[0]=ffma2(wA.x,v.x,a01[0]); a23[0]=ffma2(wA.x,v.y,a23[0]);
            a01[1]=ffma2(wA.y,v.x,a01[1]); a23[1]=ffma2(wA.y,v.y,a23[1]);
            a01[2]=ffma2(wB.x,v.x,a01[2]); a23[2]=ffma2(wB.x,v.y,a23[2]);
            a01[3]=ffma2(wB.y,v.x,a01[3]); a23[3]=ffma2(wB.y,v.y,a23[3]);
        }
        #pragma unroll
        for(int oi=0;oi<4;oi++){
            int o = half*64 + o0 + oi;
            float bb = __ldg(&b1[o]);
            float2 lo = upk(a01[oi]), hi = upk(a23[oi]);
            float uu[4] = { gelu_f(lo.x+bb), gelu_f(lo.y+bb), gelu_f(hi.x+bb), gelu_f(hi.y+bb) };
            #pragma unroll
            for(int sx=0;sx<4;sx++){
                p[0][sx] += uu[sx]*w2s[0][o];
                p[1][sx] += uu[sx]*w2s[1][o];
                p[2][sx] += uu[sx]*w2s[2][o];
            }
        }
    }
    #pragma unroll
    for(int j=0;j<3;j++){
        red[og][j][si+0]=p[j][0]; red[og][j][si+1]=p[j][1];
        red[og][j][si+2]=p[j][2]; red[og][j][si+3]=p[j][3];
    }
    __syncthreads();
    if(threadIdx.x < 64){
        int ss = threadIdx.x;
        #pragma unroll
        for(int j=0;j<3;j++){
            float acc = __ldg(&b2[j]);
            #pragma unroll
            for(int gq=0;gq<16;gq++) acc += red[gq][j][ss];
            out[(size_t)j*S3 + s0 + ss] = acc;
        }
    }
}

// ---------------- launch ----------------
extern "C" void kernel_launch(void* const* d_in, const int* in_sizes, int n_in,
                              void* d_out, int out_size){
    const float* x      = (const float*)d_in[0];
    const float* latent = (const float*)d_in[1];
    const float* lift_w = (const float*)d_in[2];
    const float* lift_b = (const float*)d_in[3];
    const float* sc_w1  = (const float*)d_in[4];
    const float* sc_w2  = (const float*)d_in[5];
    const float* sc_w3  = (const float*)d_in[6];
    const float* sc_w4  = (const float*)d_in[7];
    const float* conv_w = (const float*)d_in[8];
    const float* conv_b = (const float*)d_in[9];
    const float* gn_g   = (const float*)d_in[10];
    const float* gn_b   = (const float*)d_in[11];
    const float* p1_w   = (const float*)d_in[12];
    const float* p1_b   = (const float*)d_in[13];
    const float* p2_w   = (const float*)d_in[14];
    const float* p2_b   = (const float*)d_in[15];
    const float* c1_w   = (const float*)d_in[16];
    const float* c1_b   = (const float*)d_in[17];
    const float* c2_w   = (const float*)d_in[18];
    const float* c2_b   = (const float*)d_in[19];
    float* out = (float*)d_out;

    // Order keeps the ncu capture landing on fwdWH_k (the kernel under test this round).
    init_tables_k<<<6,256>>>();
    film1_k<<<128,256>>>(latent, c1_w, c1_b);
    lift_conv_k<<<2048,256>>>(x, lift_w, lift_b, conv_w, conv_b);

    const size_t WOFF = (size_t)64*64*12*12*12*2;
    for(int l=0;l<3;l++){
        fwdWH_k<<<dim3(32,64),128>>>();
        if(l==0) film2_k<<<48,256>>>(c2_w, c2_b);
        fwdD_k<<<dim3(24,64),128>>>();
        mix_k<<<dim3(108,8),256>>>(sc_w1 + l*WOFF, sc_w2 + l*WOFF,
                                   sc_w3 + l*WOFF, sc_w4 + l*WOFF);
        invD_k<<<dim3(24,64),128>>>();
        invHW_gn_k<<<dim3(64,64),128>>>();
        gn_final_k<<<1,32>>>();
        if(l<2)
            gn_apply_conv_k<<<2048,256>>>(gn_g + l*64, gn_b + l*64, l,
                                          conv_w + (l+1)*4096, conv_b + (l+1)*64);
        else
            gn_apply_head_k<<<4096,256>>>(gn_g + l*64, gn_b + l*64, l,
                                          p1_w, p1_b, p2_w, p2_b, out);
    }
}

// round 12
// speedup vs baseline: 1.0210x; 1.0210x over previous
#include <cuda_runtime.h>
#include <math.h>

#define S3 262144        // 64^3
#define NMODE 6912       // 4 corners * 1728

// ---------------- scratch ----------------
__device__ float  g_v[64*S3];
__device__ float  g_s[64*S3];
__device__ float2 g_B[64*64*288];
__device__ float2 g_X[64*NMODE];   // corner-major: c*NMODE + corner*1728 + cmode
__device__ float2 g_Y[64*NMODE];
__device__ float  g_h1[1024];
__device__ float  g_film[384];
__device__ double g_gn[16];
__device__ float  g_gnf[16];
__device__ __align__(16) float2 tw_fWt[64*12];   // [w][kw]  fwd W twiddle (c,-s), transposed
__device__ __align__(16) float2 tw_iW[12*64];    // [kw][w]  inv W twiddle * alpha/64^3 (c,s)
__device__ __align__(16) float2 tw_fDHt[64*24];  // [x][j]   fwd D/H twiddle (c,-s), transposed
__device__ __align__(16) float2 tw_iDH[24*64];   // [j][x]   inv D/H twiddle (c,s)

__device__ __forceinline__ float gelu_f(float x){
    return 0.5f*x*(1.0f + erff(x*0.7071067811865476f));
}

#define CMAC(acc, a, t) { acc.x += a.x*t.x - a.y*t.y; acc.y += a.x*t.y + a.y*t.x; }

// ---------------- tables ----------------
__global__ void init_tables_k(){
    int t = blockIdx.x*blockDim.x + threadIdx.x;
    const double w0 = 6.283185307179586476925286766559/64.0;
    if(t < 768){
        int kw = t>>6, w = t&63;
        double s,c; sincos(w0*(double)(kw*w), &s, &c);
        tw_fWt[w*12+kw] = make_float2((float)c, (float)(-s));
        double al = (kw==0 ? 1.0 : 2.0) / 262144.0;
        tw_iW[kw*64+w] = make_float2((float)(al*c), (float)(al*s));
    }
    if(t < 1536){
        int j = t>>6, x = t&63;
        int bin = (j<12) ? j : (j+40);
        double s,c; sincos(w0*(double)(bin*x), &s, &c);
        tw_fDHt[x*24+j] = make_float2((float)c, (float)(-s));
        tw_iDH[j*64+x]  = make_float2((float)c, (float)( s));
    }
    if(t < 16) g_gn[t] = 0.0;
}

// ---------------- FiLM ----------------
__global__ void film1_k(const float* __restrict__ latent, const float* __restrict__ w,
                        const float* __restrict__ b){
    int wid  = (blockIdx.x*blockDim.x + threadIdx.x) >> 5;
    int lane = threadIdx.x & 31;
    if(wid >= 1024) return;
    const float* wr = w + wid*512;
    float acc = 0.f;
    for(int k=lane;k<512;k+=32) acc += latent[k]*wr[k];
    #pragma unroll
    for(int o=16;o;o>>=1) acc += __shfl_xor_sync(0xffffffffu, acc, o);
    if(lane==0) g_h1[wid] = gelu_f(acc + b[wid]);
}
__global__ void film2_k(const float* __restrict__ w, const float* __restrict__ b){
    int wid  = (blockIdx.x*blockDim.x + threadIdx.x) >> 5;
    int lane = threadIdx.x & 31;
    if(wid >= 384) return;
    const float* wr = w + wid*1024;
    float acc = 0.f;
    for(int k=lane;k<1024;k+=32) acc += g_h1[k]*wr[k];
    #pragma unroll
    for(int o=16;o;o>>=1) acc += __shfl_xor_sync(0xffffffffu, acc, o);
    if(lane==0) g_film[wid] = acc + b[wid];
}

// ---------------- lift + conv(layer0), register-tiled (R4 form) ----------------
__global__ void __launch_bounds__(256) lift_conv_k(const float* __restrict__ x,
        const float* __restrict__ lw, const float* __restrict__ lb,
        const float* __restrict__ cw, const float* __restrict__ cb){
    int s0 = blockIdx.x*128;
    __shared__ float vsh[64][128];
    __shared__ float wshT[64][68];
    int s = threadIdx.x & 127, chalf = threadIdx.x >> 7;
    float x0 = __ldg(&x[s0+s]),        x1 = __ldg(&x[S3+s0+s]);
    float x2 = __ldg(&x[2*S3+s0+s]),   x3 = __ldg(&x[3*S3+s0+s]);
    for(int i=threadIdx.x;i<4096;i+=256) wshT[i&63][i>>6] = cw[i];
    #pragma unroll
    for(int i=0;i<32;i++){
        int cc = i*2 + chalf;
        float v = __ldg(&lb[cc]) + __ldg(&lw[cc*4+0])*x0 + __ldg(&lw[cc*4+1])*x1
                                 + __ldg(&lw[cc*4+2])*x2 + __ldg(&lw[cc*4+3])*x3;
        vsh[cc][s] = v;
        g_v[(size_t)cc*S3 + s0 + s] = v;
    }
    __syncthreads();
    int o0 = (threadIdx.x>>5)*8, si = (threadIdx.x&31)*4;
    float acc[8][4];
    #pragma unroll
    for(int a=0;a<8;a++){ acc[a][0]=0.f;acc[a][1]=0.f;acc[a][2]=0.f;acc[a][3]=0.f; }
    for(int k=0;k<64;k++){
        float4 v4 = *(const float4*)&vsh[k][si];
        float4 wa = *(const float4*)&wshT[k][o0];
        float4 wb = *(const float4*)&wshT[k][o0+4];
        acc[0][0]+=wa.x*v4.x; acc[0][1]+=wa.x*v4.y; acc[0][2]+=wa.x*v4.z; acc[0][3]+=wa.x*v4.w;
        acc[1][0]+=wa.y*v4.x; acc[1][1]+=wa.y*v4.y; acc[1][2]+=wa.y*v4.z; acc[1][3]+=wa.y*v4.w;
        acc[2][0]+=wa.z*v4.x; acc[2][1]+=wa.z*v4.y; acc[2][2]+=wa.z*v4.z; acc[2][3]+=wa.z*v4.w;
        acc[3][0]+=wa.w*v4.x; acc[3][1]+=wa.w*v4.y; acc[3][2]+=wa.w*v4.z; acc[3][3]+=wa.w*v4.w;
        acc[4][0]+=wb.x*v4.x; acc[4][1]+=wb.x*v4.y; acc[4][2]+=wb.x*v4.z; acc[4][3]+=wb.x*v4.w;
        acc[5][0]+=wb.y*v4.x; acc[5][1]+=wb.y*v4.y; acc[5][2]+=wb.y*v4.z; acc[5][3]+=wb.y*v4.w;
        acc[6][0]+=wb.z*v4.x; acc[6][1]+=wb.z*v4.y; acc[6][2]+=wb.z*v4.z; acc[6][3]+=wb.z*v4.w;
        acc[7][0]+=wb.w*v4.x; acc[7][1]+=wb.w*v4.y; acc[7][2]+=wb.w*v4.z; acc[7][3]+=wb.w*v4.w;
    }
    #pragma unroll
    for(int oi=0;oi<8;oi++){
        float bb = __ldg(&cb[o0+oi]);
        *(float4*)&g_s[(size_t)(o0+oi)*S3 + s0 + si] =
            make_float4(acc[oi][0]+bb, acc[oi][1]+bb, acc[oi][2]+bb, acc[oi][3]+bb);
    }
}

// ---------------- fused forward DFT: W then H, register-tiled GEMM form ----------------
// 4 d-planes per block, 128 threads, dynamic smem:
//   vT  [4][64][68]  (w-major transposed input)
//   Ash [4][64][26]  (stage-1 output, [h][kw-ri])
#define FWD_SMEM (4*64*68*4 + 4*64*26*4)

__global__ void __launch_bounds__(128) fwdWH_k(){
    extern __shared__ __align__(16) float sm[];
    float* vT  = sm;               // [p][w][68]
    float* Ash = sm + 4*64*68;     // [p][h][26]
    int d0 = blockIdx.x*4, c = blockIdx.y;

    // stage 0: load 4 planes and transpose to w-major
    for(int i=threadIdx.x; i<4096; i+=128){
        int p = i>>10, j = i&1023;
        float4 v4 = *(const float4*)(g_v + (size_t)(c*64+d0+p)*4096 + j*4);
        int h = j>>4, w4 = (j&15)*4;
        float* base = vT + (size_t)(p*64 + w4)*68 + h;
        base[0] = v4.x; base[68] = v4.y; base[136] = v4.z; base[204] = v4.w;
    }
    __syncthreads();

    // stage 1: W-DFT.  thread = (plane, 4h, 6kw-complex) -> 48 acc
    {
        int p = threadIdx.x>>5, u = threadIdx.x&31;
        int hg = u&15, kw0 = (u>>4)*6;
        float re[6][4], im[6][4];
        #pragma unroll
        for(int j=0;j<6;j++){ re[j][0]=re[j][1]=re[j][2]=re[j][3]=0.f;
                              im[j][0]=im[j][1]=im[j][2]=im[j][3]=0.f; }
        const float* vrow = vT + (size_t)p*64*68 + hg*4;
        for(int w=0;w<64;w++){
            float4 v4 = *(const float4*)(vrow + w*68);
            const float4* twp = (const float4*)(tw_fWt + w*12 + kw0);
            float4 t0 = __ldg(twp), t1 = __ldg(twp+1), t2 = __ldg(twp+2);
            float tc[6] = {t0.x, t0.z, t1.x, t1.z, t2.x, t2.z};
            float ts[6] = {t0.y, t0.w, t1.y, t1.w, t2.y, t2.w};
            #pragma unroll
            for(int j=0;j<6;j++){
                re[j][0]+=v4.x*tc[j]; re[j][1]+=v4.y*tc[j]; re[j][2]+=v4.z*tc[j]; re[j][3]+=v4.w*tc[j];
                im[j][0]+=v4.x*ts[j]; im[j][1]+=v4.y*ts[j]; im[j][2]+=v4.z*ts[j]; im[j][3]+=v4.w*ts[j];
            }
        }
        #pragma unroll
        for(int j=0;j<6;j++){
            #pragma unroll
            for(int i=0;i<4;i++){
                float* a = Ash + (size_t)(p*64 + hg*4+i)*26 + 2*(kw0+j);
                a[0]=re[j][i]; a[1]=im[j][i];
            }
        }
    }
    __syncthreads();

    // stage 2: H-DFT. thread = (plane, 3jh, 3kw) complex tiles
    {
        int p = threadIdx.x>>5, u = threadIdx.x&31;
        int jh0 = (u>>2)*3, kw0 = (u&3)*3;
        float bre[3][3], bim[3][3];
        #pragma unroll
        for(int a=0;a<3;a++){ bre[a][0]=bre[a][1]=bre[a][2]=0.f;
                              bim[a][0]=bim[a][1]=bim[a][2]=0.f; }
        const float* abase = Ash + (size_t)p*64*26 + 2*kw0;
        for(int h=0;h<64;h++){
            const float* arow = abase + h*26;
            float2 A0 = *(const float2*)(arow);
            float2 A1 = *(const float2*)(arow+2);
            float2 A2 = *(const float2*)(arow+4);
            float2 t0 = __ldg(&tw_fDHt[h*24+jh0]);
            float2 t1 = __ldg(&tw_fDHt[h*24+jh0+1]);
            float2 t2 = __ldg(&tw_fDHt[h*24+jh0+2]);
            #define HM(jj,kk,A,T) { bre[jj][kk]+=A.x*T.x - A.y*T.y; bim[jj][kk]+=A.x*T.y + A.y*T.x; }
            HM(0,0,A0,t0) HM(0,1,A1,t0) HM(0,2,A2,t0)
            HM(1,0,A0,t1) HM(1,1,A1,t1) HM(1,2,A2,t1)
            HM(2,0,A0,t2) HM(2,1,A1,t2) HM(2,2,A2,t2)
            #undef HM
        }
        float2* dst = g_B + (size_t)(c*64+d0+p)*288;
        #pragma unroll
        for(int jj=0;jj<3;jj++)
            #pragma unroll
            for(int kk=0;kk<3;kk++)
                dst[(jh0+jj)*12 + kw0+kk] = make_float2(bre[jj][kk], bim[jj][kk]);
    }
}

// ---------------- forward DFT over D (stores corner-major) ----------------
__global__ void __launch_bounds__(128) fwdD_k(){
    int jh = blockIdx.x, c = blockIdx.y;
    __shared__ float2 Bsh[64][12];
    for(int i=threadIdx.x;i<768;i+=128){
        int d = i/12, kw = i - d*12;
        Bsh[d][kw] = g_B[(size_t)(c*64+d)*288 + jh*12 + kw];
    }
    __syncthreads();
    if(threadIdx.x < 96){
        int kw = threadIdx.x % 12, jd0 = (threadIdx.x/12)*3;
        float2 b0={0,0},b1={0,0},b2={0,0};
        for(int d=0;d<64;d++){
            float2 a = Bsh[d][kw];
            float2 t0 = __ldg(&tw_fDHt[d*24+jd0]);
            float2 t1 = __ldg(&tw_fDHt[d*24+jd0+1]);
            float2 t2 = __ldg(&tw_fDHt[d*24+jd0+2]);
            CMAC(b0,a,t0); CMAC(b1,a,t1); CMAC(b2,a,t2);
        }
        int jhm = jh % 12, cbase = (jh>=12) ? 2 : 0;
        #pragma unroll
        for(int r=0;r<3;r++){
            int jd = jd0 + r;
            int corner = cbase + (jd>=12 ? 1 : 0);
            int cmode = ((jd%12)*12 + jhm)*12 + kw;
            float2 b = (r==0)?b0:(r==1)?b1:b2;
            g_X[(size_t)c*NMODE + corner*1728 + cmode] = b;
        }
    }
}

// ---------------- per-mode channel mix: float4 streaming ----------------
__global__ void __launch_bounds__(256) mix_k(const float* __restrict__ w1, const float* __restrict__ w2,
                                             const float* __restrict__ w3, const float* __restrict__ w4){
    int corner = blockIdx.x / 27;
    int c0 = (blockIdx.x - corner*27) * 64;
    const float* wbase = (corner==0)?w1:(corner==1)?w2:(corner==2)?w3:w4;
    __shared__ float2 xs[64][64];
    int tx = threadIdx.x & 31, ty = threadIdx.x >> 5;
    for(int i=ty; i<64; i+=8)
        ((float4*)xs[i])[tx] = *(const float4*)(&g_X[(size_t)i*NMODE + corner*1728 + c0 + tx*2]);
    __syncthreads();
    int o = blockIdx.y*8 + ty;
    const float* Wp = wbase + ((size_t)o*1728 + c0 + tx*2)*2;
    float re0=0.f,im0=0.f,re1=0.f,im1=0.f;
    #pragma unroll 8
    for(int i=0;i<64;i++){
        float4 wv = *(const float4*)(Wp + (size_t)i*221184);
        float4 xx = ((const float4*)xs[i])[tx];
        re0 += xx.x*wv.x - xx.y*wv.y; im0 += xx.x*wv.y + xx.y*wv.x;
        re1 += xx.z*wv.z - xx.w*wv.w; im1 += xx.z*wv.w + xx.w*wv.z;
    }
    *(float4*)(&g_Y[(size_t)o*NMODE + corner*1728 + c0 + tx*2]) = make_float4(re0,im0,re1,im1);
}

// ---------------- inverse DFT over D (reads corner-major) ----------------
__global__ void __launch_bounds__(128) invD_k(){
    int jh = blockIdx.x, c = blockIdx.y;
    __shared__ __align__(16) float2 Ysh[24][12];
    int jhm = jh % 12, cbase = (jh>=12) ? 2 : 0;
    for(int i=threadIdx.x;i<288;i+=128){
        int jd = i/12, kw = i - jd*12;
        int corner = cbase + (jd>=12 ? 1 : 0);
        int cmode = ((jd%12)*12 + jhm)*12 + kw;
        Ysh[jd][kw] = g_Y[(size_t)c*NMODE + corner*1728 + cmode];
    }
    __syncthreads();
    int d = threadIdx.x & 63, kw0 = (threadIdx.x>>6)*6;
    float2 a0={0,0},a1={0,0},a2={0,0},a3={0,0},a4={0,0},a5={0,0};
    for(int jd=0;jd<24;jd++){
        float2 t = __ldg(&tw_iDH[jd*64+d]);
        const float4* yp = (const float4*)(&Ysh[jd][kw0]);
        float4 y0 = yp[0], y1 = yp[1], y2 = yp[2];
        float2 v;
        v = make_float2(y0.x,y0.y); CMAC(a0,v,t);
        v = make_float2(y0.z,y0.w); CMAC(a1,v,t);
        v = make_float2(y1.x,y1.y); CMAC(a2,v,t);
        v = make_float2(y1.z,y1.w); CMAC(a3,v,t);
        v = make_float2(y2.x,y2.y); CMAC(a4,v,t);
        v = make_float2(y2.z,y2.w); CMAC(a5,v,t);
    }
    float2* dst = g_B + (size_t)(c*64+d)*288 + jh*12 + kw0;
    dst[0]=a0; dst[1]=a1; dst[2]=a2; dst[3]=a3; dst[4]=a4; dst[5]=a5;
}

// ---------------- fused inverse H + W + residual add + GN stats, GEMM form ----------------
// 2 d-planes per block, 128 threads.
__global__ void __launch_bounds__(128) invHW_gn_k(){
    int d0 = blockIdx.x*2, c = blockIdx.y;
    __shared__ __align__(16) float2 Bsh[2][288];
    __shared__ __align__(16) float Ash[2][64][26];
    __shared__ __align__(16) float T2[24][68];
    __shared__ float redS[4], redQ[4];

    for(int i=threadIdx.x;i<576;i+=128){
        int p = (i>=288) ? 1 : 0;
        int idx = i - p*288;
        Bsh[p][idx] = g_B[(size_t)(c*64+d0+p)*288 + idx];
    }
    for(int i=threadIdx.x;i<1536;i+=128){
        int k = i>>6, w = i&63;
        float2 t = tw_iW[(k>>1)*64 + w];
        T2[k][w] = (k&1) ? -t.y : t.x;
    }
    __syncthreads();

    // stage A: inverse H. thread = (plane, 2h, 6kw-complex) -> 24 acc
    {
        int p = threadIdx.x>>6, u = threadIdx.x&63;
        int h0 = (u&31)*2, kw0 = (u>>5)*6;
        float are[2][6], aim[2][6];
        #pragma unroll
        for(int i=0;i<2;i++)
            #pragma unroll
            for(int j=0;j<6;j++){ are[i][j]=0.f; aim[i][j]=0.f; }
        for(int jh=0;jh<24;jh++){
            float4 tt = __ldg((const float4*)&tw_iDH[jh*64+h0]);  // t(h0), t(h0+1)
            const float4* bp = (const float4*)&Bsh[p][jh*12+kw0];
            float4 b0 = bp[0], b1 = bp[1], b2 = bp[2];            // 6 complex
            float br[6] = {b0.x, b0.z, b1.x, b1.z, b2.x, b2.z};
            float bi[6] = {b0.y, b0.w, b1.y, b1.w, b2.y, b2.w};
            #pragma unroll
            for(int j=0;j<6;j++){
                are[0][j] += br[j]*tt.x - bi[j]*tt.y;
                aim[0][j] += br[j]*tt.y + bi[j]*tt.x;
                are[1][j] += br[j]*tt.z - bi[j]*tt.w;
                aim[1][j] += br[j]*tt.w + bi[j]*tt.z;
            }
        }
        #pragma unroll
        for(int i=0;i<2;i++)
            #pragma unroll
            for(int j=0;j<6;j++){
                float* a = &Ash[p][h0+i][2*(kw0+j)];
                a[0]=are[i][j]; a[1]=aim[i][j];
            }
    }
    __syncthreads();

    // stage B: inverse W as real GEMM (K=24) + residual + GN stats
    int wg = threadIdx.x&7, hg = threadIdx.x>>3;   // wg: 8w, hg: 4h
    float ssum=0.f, sq=0.f;
    for(int p=0;p<2;p++){
        float acc[4][8];
        #pragma unroll
        for(int i=0;i<4;i++)
            #pragma unroll
            for(int j=0;j<8;j++) acc[i][j]=0.f;
        for(int k=0;k<24;k++){
            float4 Tw0 = *(const float4*)&T2[k][wg*8];
            float4 Tw1 = *(const float4*)&T2[k][wg*8+4];
            float a0 = Ash[p][hg*4+0][k];
            float a1 = Ash[p][hg*4+1][k];
            float a2 = Ash[p][hg*4+2][k];
            float a3 = Ash[p][hg*4+3][k];
            acc[0][0]+=a0*Tw0.x; acc[0][1]+=a0*Tw0.y; acc[0][2]+=a0*Tw0.z; acc[0][3]+=a0*Tw0.w;
            acc[0][4]+=a0*Tw1.x; acc[0][5]+=a0*Tw1.y; acc[0][6]+=a0*Tw1.z; acc[0][7]+=a0*Tw1.w;
            acc[1][0]+=a1*Tw0.x; acc[1][1]+=a1*Tw0.y; acc[1][2]+=a1*Tw0.z; acc[1][3]+=a1*Tw0.w;
            acc[1][4]+=a1*Tw1.x; acc[1][5]+=a1*Tw1.y; acc[1][6]+=a1*Tw1.z; acc[1][7]+=a1*Tw1.w;
            acc[2][0]+=a2*Tw0.x; acc[2][1]+=a2*Tw0.y; acc[2][2]+=a2*Tw0.z; acc[2][3]+=a2*Tw0.w;
            acc[2][4]+=a2*Tw1.x; acc[2][5]+=a2*Tw1.y; acc[2][6]+=a2*Tw1.z; acc[2][7]+=a2*Tw1.w;
            acc[3][0]+=a3*Tw0.x; acc[3][1]+=a3*Tw0.y; acc[3][2]+=a3*Tw0.z; acc[3][3]+=a3*Tw0.w;
            acc[3][4]+=a3*Tw1.x; acc[3][5]+=a3*Tw1.y; acc[3][6]+=a3*Tw1.z; acc[3][7]+=a3*Tw1.w;
        }
        float* srow = g_s + (size_t)c*S3 + (size_t)(d0+p)*4096;
        #pragma unroll
        for(int i=0;i<4;i++){
            int h = hg*4+i;
            float4* q = (float4*)(srow + h*64 + wg*8);
            float4 s0 = q[0], s1 = q[1];
            s0.x+=acc[i][0]; s0.y+=acc[i][1]; s0.z+=acc[i][2]; s0.w+=acc[i][3];
            s1.x+=acc[i][4]; s1.y+=acc[i][5]; s1.z+=acc[i][6]; s1.w+=acc[i][7];
            q[0]=s0; q[1]=s1;
            ssum += s0.x+s0.y+s0.z+s0.w + s1.x+s1.y+s1.z+s1.w;
            sq   += s0.x*s0.x+s0.y*s0.y+s0.z*s0.z+s0.w*s0.w
                  + s1.x*s1.x+s1.y*s1.y+s1.z*s1.z+s1.w*s1.w;
        }
    }
    #pragma unroll
    for(int o=16;o;o>>=1){ ssum += __shfl_xor_sync(0xffffffffu,ssum,o);
                           sq   += __shfl_xor_sync(0xffffffffu,sq,o); }
    int wp = threadIdx.x & 31, warp = threadIdx.x >> 5;
    if(wp==0){ redS[warp]=ssum; redQ[warp]=sq; }
    __syncthreads();
    if(threadIdx.x==0){
        float S = redS[0]+redS[1]+redS[2]+redS[3];
        float Q = redQ[0]+redQ[1]+redQ[2]+redQ[3];
        int g = c>>3;
        atomicAdd(&g_gn[g*2],   (double)S);
        atomicAdd(&g_gn[g*2+1], (double)Q);
    }
}

__global__ void gn_final_k(){
    int g = threadIdx.x;
    float mu_f=0.f, rs_f=0.f;
    if(g<8){
        double n = 8.0*(double)S3;
        double mu = g_gn[g*2]/n;
        double var = g_gn[g*2+1]/n - mu*mu;
        mu_f = (float)mu; rs_f = (float)(1.0/sqrt(var + 1e-5));
    }
    __syncthreads();
    if(g<8){ g_gnf[g*2]=mu_f; g_gnf[g*2+1]=rs_f; }
    if(g<16) g_gn[g]=0.0;
}

// ---------------- GN-apply + GELU + FiLM + conv(next layer) (R4 form) ----------------
__global__ void __launch_bounds__(256) gn_apply_conv_k(const float* __restrict__ gg, const float* __restrict__ gb,
        int l, const float* __restrict__ cw, const float* __restrict__ cb){
    int s0 = blockIdx.x*128;
    __shared__ float vsh[64][128];
    __shared__ float wshT[64][68];
    int s = threadIdx.x & 127, chalf = threadIdx.x >> 7;
    for(int i=threadIdx.x;i<4096;i+=256) wshT[i&63][i>>6] = cw[i];
    #pragma unroll
    for(int i=0;i<32;i++){
        int cc = i*2 + chalf;
        int g = cc>>3;
        float xv = (g_s[(size_t)cc*S3+s0+s]-g_gnf[g*2])*g_gnf[g*2+1]*__ldg(&gg[cc]) + __ldg(&gb[cc]);
        float y = gelu_f(xv);
        float v = y*(1.f+g_film[(l*64+cc)*2]) + g_film[(l*64+cc)*2+1];
        vsh[cc][s] = v;
        g_v[(size_t)cc*S3+s0+s] = v;
    }
    __syncthreads();
    int o0 = (threadIdx.x>>5)*8, si = (threadIdx.x&31)*4;
    float acc[8][4];
    #pragma unroll
    for(int a=0;a<8;a++){ acc[a][0]=0.f;acc[a][1]=0.f;acc[a][2]=0.f;acc[a][3]=0.f; }
    for(int k=0;k<64;k++){
        float4 v4 = *(const float4*)&vsh[k][si];
        float4 wa = *(const float4*)&wshT[k][o0];
        float4 wb = *(const float4*)&wshT[k][o0+4];
        acc[0][0]+=wa.x*v4.x; acc[0][1]+=wa.x*v4.y; acc[0][2]+=wa.x*v4.z; acc[0][3]+=wa.x*v4.w;
        acc[1][0]+=wa.y*v4.x; acc[1][1]+=wa.y*v4.y; acc[1][2]+=wa.y*v4.z; acc[1][3]+=wa.y*v4.w;
        acc[2][0]+=wa.z*v4.x; acc[2][1]+=wa.z*v4.y; acc[2][2]+=wa.z*v4.z; acc[2][3]+=wa.z*v4.w;
        acc[3][0]+=wa.w*v4.x; acc[3][1]+=wa.w*v4.y; acc[3][2]+=wa.w*v4.z; acc[3][3]+=wa.w*v4.w;
        acc[4][0]+=wb.x*v4.x; acc[4][1]+=wb.x*v4.y; acc[4][2]+=wb.x*v4.z; acc[4][3]+=wb.x*v4.w;
        acc[5][0]+=wb.y*v4.x; acc[5][1]+=wb.y*v4.y; acc[5][2]+=wb.y*v4.z; acc[5][3]+=wb.y*v4.w;
        acc[6][0]+=wb.z*v4.x; acc[6][1]+=wb.z*v4.y; acc[6][2]+=wb.z*v4.z; acc[6][3]+=wb.z*v4.w;
        acc[7][0]+=wb.w*v4.x; acc[7][1]+=wb.w*v4.y; acc[7][2]+=wb.w*v4.z; acc[7][3]+=wb.w*v4.w;
    }
    #pragma unroll
    for(int oi=0;oi<8;oi++){
        float bb = __ldg(&cb[o0+oi]);
        *(float4*)&g_s[(size_t)(o0+oi)*S3 + s0 + si] =
            make_float4(acc[oi][0]+bb, acc[oi][1]+bb, acc[oi][2]+bb, acc[oi][3]+bb);
    }
}

// ---------------- last layer: GN-apply + FiLM + p1 + GELU + p2 (R4 form) ----------------
__global__ void __launch_bounds__(256) gn_apply_head_k(const float* __restrict__ gg, const float* __restrict__ gb,
        int l, const float* __restrict__ w1, const float* __restrict__ b1,
        const float* __restrict__ w2, const float* __restrict__ b2, float* __restrict__ out){
    int s0 = blockIdx.x*64;
    __shared__ float vsh[64][64];
    __shared__ float wshT[64][68];
    __shared__ float w2s[3][128];
    __shared__ float red[16][3][64];
    int s = threadIdx.x & 63, cq = threadIdx.x >> 6;
    for(int i=threadIdx.x;i<384;i+=256){ int j=i>>7, o=i&127; w2s[j][o]=w2[j*128+o]; }
    #pragma unroll
    for(int i=0;i<16;i++){
        int cc = i*4 + cq;
        int g = cc>>3;
        float xv = (g_s[(size_t)cc*S3+s0+s]-g_gnf[g*2])*g_gnf[g*2+1]*__ldg(&gg[cc]) + __ldg(&gb[cc]);
        float y = gelu_f(xv);
        vsh[cc][s] = y*(1.f+g_film[(l*64+cc)*2]) + g_film[(l*64+cc)*2+1];
    }
    int og = threadIdx.x >> 4, sg = threadIdx.x & 15;
    int o0 = og*4, si = sg*4;
    float p[3][4];
    #pragma unroll
    for(int j=0;j<3;j++){ p[j][0]=0.f;p[j][1]=0.f;p[j][2]=0.f;p[j][3]=0.f; }
    for(int half=0; half<2; half++){
        __syncthreads();
        for(int i=threadIdx.x;i<4096;i+=256){ int o=i>>6,k=i&63; wshT[k][o]=w1[(half*64+o)*64+k]; }
        __syncthreads();
        float acc[4][4];
        #pragma unroll
        for(int a=0;a<4;a++){ acc[a][0]=0.f;acc[a][1]=0.f;acc[a][2]=0.f;acc[a][3]=0.f; }
        for(int k=0;k<64;k++){
            float4 v4 = *(const float4*)&vsh[k][si];
            float4 wv = *(const float4*)&wshT[k][o0];
            acc[0][0]+=wv.x*v4.x; acc[0][1]+=wv.x*v4.y; acc[0][2]+=wv.x*v4.z; acc[0][3]+=wv.x*v4.w;
            acc[1][0]+=wv.y*v4.x; acc[1][1]+=wv.y*v4.y; acc[1][2]+=wv.y*v4.z; acc[1][3]+=wv.y*v4.w;
            acc[2][0]+=wv.z*v4.x; acc[2][1]+=wv.z*v4.y; acc[2][2]+=wv.z*v4.z; acc[2][3]+=wv.z*v4.w;
            acc[3][0]+=wv.w*v4.x; acc[3][1]+=wv.w*v4.y; acc[3][2]+=wv.w*v4.z; acc[3][3]+=wv.w*v4.w;
        }
        #pragma unroll
        for(int oi=0;oi<4;oi++){
            int o = half*64 + o0 + oi;
            float bb = __ldg(&b1[o]);
            #pragma unroll
            for(int sx=0;sx<4;sx++){
                float u = gelu_f(acc[oi][sx] + bb);
                p[0][sx] += u*w2s[0][o];
                p[1][sx] += u*w2s[1][o];
                p[2][sx] += u*w2s[2][o];
            }
        }
    }
    #pragma unroll
    for(int j=0;j<3;j++){
        red[og][j][si+0]=p[j][0]; red[og][j][si+1]=p[j][1];
        red[og][j][si+2]=p[j][2]; red[og][j][si+3]=p[j][3];
    }
    __syncthreads();
    if(threadIdx.x < 64){
        int ss = threadIdx.x;
        #pragma unroll
        for(int j=0;j<3;j++){
            float acc = __ldg(&b2[j]);
            #pragma unroll
            for(int gq=0;gq<16;gq++) acc += red[gq][j][ss];
            out[(size_t)j*S3 + s0 + ss] = acc;
        }
    }
}

// ---------------- launch ----------------
extern "C" void kernel_launch(void* const* d_in, const int* in_sizes, int n_in,
                              void* d_out, int out_size){
    const float* x      = (const float*)d_in[0];
    const float* latent = (const float*)d_in[1];
    const float* lift_w = (const float*)d_in[2];
    const float* lift_b = (const float*)d_in[3];
    const float* sc_w1  = (const float*)d_in[4];
    const float* sc_w2  = (const float*)d_in[5];
    const float* sc_w3  = (const float*)d_in[6];
    const float* sc_w4  = (const float*)d_in[7];
    const float* conv_w = (const float*)d_in[8];
    const float* conv_b = (const float*)d_in[9];
    const float* gn_g   = (const float*)d_in[10];
    const float* gn_b   = (const float*)d_in[11];
    const float* p1_w   = (const float*)d_in[12];
    const float* p1_b   = (const float*)d_in[13];
    const float* p2_w   = (const float*)d_in[14];
    const float* p2_b   = (const float*)d_in[15];
    const float* c1_w   = (const float*)d_in[16];
    const float* c1_b   = (const float*)d_in[17];
    const float* c2_w   = (const float*)d_in[18];
    const float* c2_b   = (const float*)d_in[19];
    float* out = (float*)d_out;

    static int smem_set = 0;
    if(!smem_set){
        cudaFuncSetAttribute(fwdWH_k, cudaFuncAttributeMaxDynamicSharedMemorySize, FWD_SMEM);
        smem_set = 1;
    }

    // Order keeps the ncu capture landing on fwdWH_k (4th launch).
    init_tables_k<<<6,256>>>();
    film1_k<<<128,256>>>(latent, c1_w, c1_b);
    lift_conv_k<<<2048,256>>>(x, lift_w, lift_b, conv_w, conv_b);

    const size_t WOFF = (size_t)64*64*12*12*12*2;
    for(int l=0;l<3;l++){
        fwdWH_k<<<dim3(16,64),128,FWD_SMEM>>>();
        if(l==0) film2_k<<<48,256>>>(c2_w, c2_b);
        fwdD_k<<<dim3(24,64),128>>>();
        mix_k<<<dim3(108,8),256>>>(sc_w1 + l*WOFF, sc_w2 + l*WOFF,
                                   sc_w3 + l*WOFF, sc_w4 + l*WOFF);
        invD_k<<<dim3(24,64),128>>>();
        invHW_gn_k<<<dim3(32,64),128>>>();
        gn_final_k<<<1,32>>>();
        if(l<2)
            gn_apply_conv_k<<<2048,256>>>(gn_g + l*64, gn_b + l*64, l,
                                          conv_w + (l+1)*4096, conv_b + (l+1)*64);
        else
            gn_apply_head_k<<<4096,256>>>(gn_g + l*64, gn_b + l*64, l,
                                          p1_w, p1_b, p2_w, p2_b, out);
    }
}

// round 13
// speedup vs baseline: 1.0493x; 1.0277x over previous
#include <cuda_runtime.h>
#include <math.h>

#define S3 262144        // 64^3
#define NMODE 6912       // 4 corners * 1728

// ---------------- scratch ----------------
__device__ float  g_v[64*S3];
__device__ float  g_s[64*S3];
__device__ float2 g_B[64*64*288];
__device__ float2 g_X[64*NMODE];   // corner-major: c*NMODE + corner*1728 + cmode
__device__ float2 g_Y[64*NMODE];
__device__ float  g_h1[1024];
__device__ float  g_film[384];
__device__ double g_gn[16];
__device__ float  g_gnf[16];
__device__ __align__(16) float2 tw_fWt[64*12];   // [w][kw]  fwd W twiddle (c,-s), transposed
__device__ __align__(16) float2 tw_iW[12*64];    // [kw][w]  inv W twiddle * alpha/64^3 (c,s)
__device__ __align__(16) float2 tw_fDHt[64*24];  // [x][j]   fwd D/H twiddle (c,-s), transposed
__device__ __align__(16) float2 tw_iDH[24*64];   // [j][x]   inv D/H twiddle (c,s)

__device__ __forceinline__ float gelu_f(float x){
    return 0.5f*x*(1.0f + erff(x*0.7071067811865476f));
}

#define CMAC(acc, a, t) { acc.x += a.x*t.x - a.y*t.y; acc.y += a.x*t.y + a.y*t.x; }

// ---------------- tables ----------------
__global__ void init_tables_k(){
    int t = blockIdx.x*blockDim.x + threadIdx.x;
    const double w0 = 6.283185307179586476925286766559/64.0;
    if(t < 768){
        int kw = t>>6, w = t&63;
        double s,c; sincos(w0*(double)(kw*w), &s, &c);
        tw_fWt[w*12+kw] = make_float2((float)c, (float)(-s));
        double al = (kw==0 ? 1.0 : 2.0) / 262144.0;
        tw_iW[kw*64+w] = make_float2((float)(al*c), (float)(al*s));
    }
    if(t < 1536){
        int j = t>>6, x = t&63;
        int bin = (j<12) ? j : (j+40);
        double s,c; sincos(w0*(double)(bin*x), &s, &c);
        tw_fDHt[x*24+j] = make_float2((float)c, (float)(-s));
        tw_iDH[j*64+x]  = make_float2((float)c, (float)( s));
    }
    if(t < 16) g_gn[t] = 0.0;
}

// ---------------- FiLM ----------------
__global__ void film1_k(const float* __restrict__ latent, const float* __restrict__ w,
                        const float* __restrict__ b){
    int wid  = (blockIdx.x*blockDim.x + threadIdx.x) >> 5;
    int lane = threadIdx.x & 31;
    if(wid >= 1024) return;
    const float* wr = w + wid*512;
    float acc = 0.f;
    for(int k=lane;k<512;k+=32) acc += latent[k]*wr[k];
    #pragma unroll
    for(int o=16;o;o>>=1) acc += __shfl_xor_sync(0xffffffffu, acc, o);
    if(lane==0) g_h1[wid] = gelu_f(acc + b[wid]);
}
__global__ void film2_k(const float* __restrict__ w, const float* __restrict__ b){
    int wid  = (blockIdx.x*blockDim.x + threadIdx.x) >> 5;
    int lane = threadIdx.x & 31;
    if(wid >= 384) return;
    const float* wr = w + wid*1024;
    float acc = 0.f;
    for(int k=lane;k<1024;k+=32) acc += g_h1[k]*wr[k];
    #pragma unroll
    for(int o=16;o;o>>=1) acc += __shfl_xor_sync(0xffffffffu, acc, o);
    if(lane==0) g_film[wid] = acc + b[wid];
}

// ---------------- lift + conv(layer0), register-tiled (R4 form) ----------------
__global__ void __launch_bounds__(256) lift_conv_k(const float* __restrict__ x,
        const float* __restrict__ lw, const float* __restrict__ lb,
        const float* __restrict__ cw, const float* __restrict__ cb){
    int s0 = blockIdx.x*128;
    __shared__ float vsh[64][128];
    __shared__ float wshT[64][68];
    int s = threadIdx.x & 127, chalf = threadIdx.x >> 7;
    float x0 = __ldg(&x[s0+s]),        x1 = __ldg(&x[S3+s0+s]);
    float x2 = __ldg(&x[2*S3+s0+s]),   x3 = __ldg(&x[3*S3+s0+s]);
    for(int i=threadIdx.x;i<4096;i+=256) wshT[i&63][i>>6] = cw[i];
    #pragma unroll
    for(int i=0;i<32;i++){
        int cc = i*2 + chalf;
        float v = __ldg(&lb[cc]) + __ldg(&lw[cc*4+0])*x0 + __ldg(&lw[cc*4+1])*x1
                                 + __ldg(&lw[cc*4+2])*x2 + __ldg(&lw[cc*4+3])*x3;
        vsh[cc][s] = v;
        g_v[(size_t)cc*S3 + s0 + s] = v;
    }
    __syncthreads();
    int o0 = (threadIdx.x>>5)*8, si = (threadIdx.x&31)*4;
    float acc[8][4];
    #pragma unroll
    for(int a=0;a<8;a++){ acc[a][0]=0.f;acc[a][1]=0.f;acc[a][2]=0.f;acc[a][3]=0.f; }
    for(int k=0;k<64;k++){
        float4 v4 = *(const float4*)&vsh[k][si];
        float4 wa = *(const float4*)&wshT[k][o0];
        float4 wb = *(const float4*)&wshT[k][o0+4];
        acc[0][0]+=wa.x*v4.x; acc[0][1]+=wa.x*v4.y; acc[0][2]+=wa.x*v4.z; acc[0][3]+=wa.x*v4.w;
        acc[1][0]+=wa.y*v4.x; acc[1][1]+=wa.y*v4.y; acc[1][2]+=wa.y*v4.z; acc[1][3]+=wa.y*v4.w;
        acc[2][0]+=wa.z*v4.x; acc[2][1]+=wa.z*v4.y; acc[2][2]+=wa.z*v4.z; acc[2][3]+=wa.z*v4.w;
        acc[3][0]+=wa.w*v4.x; acc[3][1]+=wa.w*v4.y; acc[3][2]+=wa.w*v4.z; acc[3][3]+=wa.w*v4.w;
        acc[4][0]+=wb.x*v4.x; acc[4][1]+=wb.x*v4.y; acc[4][2]+=wb.x*v4.z; acc[4][3]+=wb.x*v4.w;
        acc[5][0]+=wb.y*v4.x; acc[5][1]+=wb.y*v4.y; acc[5][2]+=wb.y*v4.z; acc[5][3]+=wb.y*v4.w;
        acc[6][0]+=wb.z*v4.x; acc[6][1]+=wb.z*v4.y; acc[6][2]+=wb.z*v4.z; acc[6][3]+=wb.z*v4.w;
        acc[7][0]+=wb.w*v4.x; acc[7][1]+=wb.w*v4.y; acc[7][2]+=wb.w*v4.z; acc[7][3]+=wb.w*v4.w;
    }
    #pragma unroll
    for(int oi=0;oi<8;oi++){
        float bb = __ldg(&cb[o0+oi]);
        *(float4*)&g_s[(size_t)(o0+oi)*S3 + s0 + si] =
            make_float4(acc[oi][0]+bb, acc[oi][1]+bb, acc[oi][2]+bb, acc[oi][3]+bb);
    }
}

// ---------------- fused forward DFT: W then H, register-tiled, 256 threads ----------------
// 4 d-planes per block, dynamic smem:
//   vT  [4][64][68]  (w-major transposed input)        69632 B
//   Ash [4][64][28]  (stage-1 out, [h][kw-ri], pad 28)  28672 B
#define FWD_SMEM (4*64*68*4 + 4*64*28*4)

__global__ void __launch_bounds__(256) fwdWH_k(){
    extern __shared__ __align__(16) float sm[];
    float* vT  = sm;               // [p][w][68]
    float* Ash = sm + 4*64*68;     // [p][h][28]
    int d0 = blockIdx.x*4, c = blockIdx.y;

    // stage 0: load 4 planes and transpose to w-major
    for(int i=threadIdx.x; i<4096; i+=256){
        int p = i>>10, j = i&1023;
        float4 v4 = *(const float4*)(g_v + (size_t)(c*64+d0+p)*4096 + j*4);
        int h = j>>4, w4 = (j&15)*4;
        float* base = vT + (size_t)(p*64 + w4)*68 + h;
        base[0] = v4.x; base[68] = v4.y; base[136] = v4.z; base[204] = v4.w;
    }
    __syncthreads();

    int p = threadIdx.x>>6, u = threadIdx.x&63;

    // stage 1: W-DFT. thread = (plane, 2h, 6kw-complex) -> 24 complex acc
    {
        int h0 = (u&31)*2, kw0 = (u>>5)*6;
        float re[6][2], im[6][2];
        #pragma unroll
        for(int j=0;j<6;j++){ re[j][0]=re[j][1]=0.f; im[j][0]=im[j][1]=0.f; }
        const float* vrow = vT + (size_t)p*64*68 + h0;
        #pragma unroll 2
        for(int w=0;w<64;w++){
            float2 v2 = *(const float2*)(vrow + w*68);
            const float4* twp = (const float4*)(tw_fWt + w*12 + kw0);
            float4 t0 = __ldg(twp), t1 = __ldg(twp+1), t2 = __ldg(twp+2);
            float tc[6] = {t0.x, t0.z, t1.x, t1.z, t2.x, t2.z};
            float ts[6] = {t0.y, t0.w, t1.y, t1.w, t2.y, t2.w};
            #pragma unroll
            for(int j=0;j<6;j++){
                re[j][0]+=v2.x*tc[j]; re[j][1]+=v2.y*tc[j];
                im[j][0]+=v2.x*ts[j]; im[j][1]+=v2.y*ts[j];
            }
        }
        #pragma unroll
        for(int i=0;i<2;i++){
            float* a = Ash + (size_t)(p*64 + h0+i)*28 + 2*kw0;
            #pragma unroll
            for(int j=0;j<6;j++){ a[2*j]=re[j][i]; a[2*j+1]=im[j][i]; }
        }
    }
    __syncthreads();

    // stage 2: H-DFT. 48 active threads/plane: (3jh x 2kw) complex tiles
    if(u < 48){
        int jh0 = (u/6)*3, kw0 = (u%6)*2;
        float bre[3][2], bim[3][2];
        #pragma unroll
        for(int a=0;a<3;a++){ bre[a][0]=bre[a][1]=0.f; bim[a][0]=bim[a][1]=0.f; }
        const float* abase = Ash + (size_t)p*64*28 + 2*kw0;
        #pragma unroll 2
        for(int h=0;h<64;h++){
            float4 A = *(const float4*)(abase + h*28);   // 2 complex (kw0, kw0+1)
            float2 A0 = make_float2(A.x, A.y);
            float2 A1 = make_float2(A.z, A.w);
            float2 t0 = __ldg(&tw_fDHt[h*24+jh0]);
            float2 t1 = __ldg(&tw_fDHt[h*24+jh0+1]);
            float2 t2 = __ldg(&tw_fDHt[h*24+jh0+2]);
            #define HM(jj,kk,AA,T) { bre[jj][kk]+=AA.x*T.x - AA.y*T.y; bim[jj][kk]+=AA.x*T.y + AA.y*T.x; }
            HM(0,0,A0,t0) HM(0,1,A1,t0)
            HM(1,0,A0,t1) HM(1,1,A1,t1)
            HM(2,0,A0,t2) HM(2,1,A1,t2)
            #undef HM
        }
        float2* dst = g_B + (size_t)(c*64+d0+p)*288;
        #pragma unroll
        for(int jj=0;jj<3;jj++){
            *(float4*)(&dst[(jh0+jj)*12 + kw0]) =
                make_float4(bre[jj][0], bim[jj][0], bre[jj][1], bim[jj][1]);
        }
    }
}

// ---------------- forward DFT over D (stores corner-major) ----------------
__global__ void __launch_bounds__(128) fwdD_k(){
    int jh = blockIdx.x, c = blockIdx.y;
    __shared__ float2 Bsh[64][12];
    for(int i=threadIdx.x;i<768;i+=128){
        int d = i/12, kw = i - d*12;
        Bsh[d][kw] = g_B[(size_t)(c*64+d)*288 + jh*12 + kw];
    }
    __syncthreads();
    if(threadIdx.x < 96){
        int kw = threadIdx.x % 12, jd0 = (threadIdx.x/12)*3;
        float2 b0={0,0},b1={0,0},b2={0,0};
        for(int d=0;d<64;d++){
            float2 a = Bsh[d][kw];
            float2 t0 = __ldg(&tw_fDHt[d*24+jd0]);
            float2 t1 = __ldg(&tw_fDHt[d*24+jd0+1]);
            float2 t2 = __ldg(&tw_fDHt[d*24+jd0+2]);
            CMAC(b0,a,t0); CMAC(b1,a,t1); CMAC(b2,a,t2);
        }
        int jhm = jh % 12, cbase = (jh>=12) ? 2 : 0;
        #pragma unroll
        for(int r=0;r<3;r++){
            int jd = jd0 + r;
            int corner = cbase + (jd>=12 ? 1 : 0);
            int cmode = ((jd%12)*12 + jhm)*12 + kw;
            float2 b = (r==0)?b0:(r==1)?b1:b2;
            g_X[(size_t)c*NMODE + corner*1728 + cmode] = b;
        }
    }
}

// ---------------- per-mode channel mix: float4 streaming ----------------
__global__ void __launch_bounds__(256) mix_k(const float* __restrict__ w1, const float* __restrict__ w2,
                                             const float* __restrict__ w3, const float* __restrict__ w4){
    int corner = blockIdx.x / 27;
    int c0 = (blockIdx.x - corner*27) * 64;
    const float* wbase = (corner==0)?w1:(corner==1)?w2:(corner==2)?w3:w4;
    __shared__ float2 xs[64][64];
    int tx = threadIdx.x & 31, ty = threadIdx.x >> 5;
    for(int i=ty; i<64; i+=8)
        ((float4*)xs[i])[tx] = *(const float4*)(&g_X[(size_t)i*NMODE + corner*1728 + c0 + tx*2]);
    __syncthreads();
    int o = blockIdx.y*8 + ty;
    const float* Wp = wbase + ((size_t)o*1728 + c0 + tx*2)*2;
    float re0=0.f,im0=0.f,re1=0.f,im1=0.f;
    #pragma unroll 8
    for(int i=0;i<64;i++){
        float4 wv = *(const float4*)(Wp + (size_t)i*221184);
        float4 xx = ((const float4*)xs[i])[tx];
        re0 += xx.x*wv.x - xx.y*wv.y; im0 += xx.x*wv.y + xx.y*wv.x;
        re1 += xx.z*wv.z - xx.w*wv.w; im1 += xx.z*wv.w + xx.w*wv.z;
    }
    *(float4*)(&g_Y[(size_t)o*NMODE + corner*1728 + c0 + tx*2]) = make_float4(re0,im0,re1,im1);
}

// ---------------- inverse DFT over D (reads corner-major) ----------------
__global__ void __launch_bounds__(128) invD_k(){
    int jh = blockIdx.x, c = blockIdx.y;
    __shared__ __align__(16) float2 Ysh[24][12];
    int jhm = jh % 12, cbase = (jh>=12) ? 2 : 0;
    for(int i=threadIdx.x;i<288;i+=128){
        int jd = i/12, kw = i - jd*12;
        int corner = cbase + (jd>=12 ? 1 : 0);
        int cmode = ((jd%12)*12 + jhm)*12 + kw;
        Ysh[jd][kw] = g_Y[(size_t)c*NMODE + corner*1728 + cmode];
    }
    __syncthreads();
    int d = threadIdx.x & 63, kw0 = (threadIdx.x>>6)*6;
    float2 a0={0,0},a1={0,0},a2={0,0},a3={0,0},a4={0,0},a5={0,0};
    for(int jd=0;jd<24;jd++){
        float2 t = __ldg(&tw_iDH[jd*64+d]);
        const float4* yp = (const float4*)(&Ysh[jd][kw0]);
        float4 y0 = yp[0], y1 = yp[1], y2 = yp[2];
        float2 v;
        v = make_float2(y0.x,y0.y); CMAC(a0,v,t);
        v = make_float2(y0.z,y0.w); CMAC(a1,v,t);
        v = make_float2(y1.x,y1.y); CMAC(a2,v,t);
        v = make_float2(y1.z,y1.w); CMAC(a3,v,t);
        v = make_float2(y2.x,y2.y); CMAC(a4,v,t);
        v = make_float2(y2.z,y2.w); CMAC(a5,v,t);
    }
    float2* dst = g_B + (size_t)(c*64+d)*288 + jh*12 + kw0;
    dst[0]=a0; dst[1]=a1; dst[2]=a2; dst[3]=a3; dst[4]=a4; dst[5]=a5;
}

// ---------------- fused inverse H + W + residual add + GN stats, GEMM form ----------------
// 2 d-planes per block, 128 threads.
__global__ void __launch_bounds__(128) invHW_gn_k(){
    int d0 = blockIdx.x*2, c = blockIdx.y;
    __shared__ __align__(16) float2 Bsh[2][288];
    __shared__ __align__(16) float Ash[2][64][26];
    __shared__ __align__(16) float T2[24][68];
    __shared__ float redS[4], redQ[4];

    for(int i=threadIdx.x;i<576;i+=128){
        int p = (i>=288) ? 1 : 0;
        int idx = i - p*288;
        Bsh[p][idx] = g_B[(size_t)(c*64+d0+p)*288 + idx];
    }
    for(int i=threadIdx.x;i<1536;i+=128){
        int k = i>>6, w = i&63;
        float2 t = tw_iW[(k>>1)*64 + w];
        T2[k][w] = (k&1) ? -t.y : t.x;
    }
    __syncthreads();

    // stage A: inverse H. thread = (plane, 2h, 6kw-complex) -> 24 acc
    {
        int p = threadIdx.x>>6, u = threadIdx.x&63;
        int h0 = (u&31)*2, kw0 = (u>>5)*6;
        float are[2][6], aim[2][6];
        #pragma unroll
        for(int i=0;i<2;i++)
            #pragma unroll
            for(int j=0;j<6;j++){ are[i][j]=0.f; aim[i][j]=0.f; }
        for(int jh=0;jh<24;jh++){
            float4 tt = __ldg((const float4*)&tw_iDH[jh*64+h0]);  // t(h0), t(h0+1)
            const float4* bp = (const float4*)&Bsh[p][jh*12+kw0];
            float4 b0 = bp[0], b1 = bp[1], b2 = bp[2];            // 6 complex
            float br[6] = {b0.x, b0.z, b1.x, b1.z, b2.x, b2.z};
            float bi[6] = {b0.y, b0.w, b1.y, b1.w, b2.y, b2.w};
            #pragma unroll
            for(int j=0;j<6;j++){
                are[0][j] += br[j]*tt.x - bi[j]*tt.y;
                aim[0][j] += br[j]*tt.y + bi[j]*tt.x;
                are[1][j] += br[j]*tt.z - bi[j]*tt.w;
                aim[1][j] += br[j]*tt.w + bi[j]*tt.z;
            }
        }
        #pragma unroll
        for(int i=0;i<2;i++)
            #pragma unroll
            for(int j=0;j<6;j++){
                float* a = &Ash[p][h0+i][2*(kw0+j)];
                a[0]=are[i][j]; a[1]=aim[i][j];
            }
    }
    __syncthreads();

    // stage B: inverse W as real GEMM (K=24) + residual + GN stats
    int wg = threadIdx.x&7, hg = threadIdx.x>>3;   // wg: 8w, hg: 4h
    float ssum=0.f, sq=0.f;
    for(int p=0;p<2;p++){
        float acc[4][8];
        #pragma unroll
        for(int i=0;i<4;i++)
            #pragma unroll
            for(int j=0;j<8;j++) acc[i][j]=0.f;
        for(int k=0;k<24;k++){
            float4 Tw0 = *(const float4*)&T2[k][wg*8];
            float4 Tw1 = *(const float4*)&T2[k][wg*8+4];
            float a0 = Ash[p][hg*4+0][k];
            float a1 = Ash[p][hg*4+1][k];
            float a2 = Ash[p][hg*4+2][k];
            float a3 = Ash[p][hg*4+3][k];
            acc[0][0]+=a0*Tw0.x; acc[0][1]+=a0*Tw0.y; acc[0][2]+=a0*Tw0.z; acc[0][3]+=a0*Tw0.w;
            acc[0][4]+=a0*Tw1.x; acc[0][5]+=a0*Tw1.y; acc[0][6]+=a0*Tw1.z; acc[0][7]+=a0*Tw1.w;
            acc[1][0]+=a1*Tw0.x; acc[1][1]+=a1*Tw0.y; acc[1][2]+=a1*Tw0.z; acc[1][3]+=a1*Tw0.w;
            acc[1][4]+=a1*Tw1.x; acc[1][5]+=a1*Tw1.y; acc[1][6]+=a1*Tw1.z; acc[1][7]+=a1*Tw1.w;
            acc[2][0]+=a2*Tw0.x; acc[2][1]+=a2*Tw0.y; acc[2][2]+=a2*Tw0.z; acc[2][3]+=a2*Tw0.w;
            acc[2][4]+=a2*Tw1.x; acc[2][5]+=a2*Tw1.y; acc[2][6]+=a2*Tw1.z; acc[2][7]+=a2*Tw1.w;
            acc[3][0]+=a3*Tw0.x; acc[3][1]+=a3*Tw0.y; acc[3][2]+=a3*Tw0.z; acc[3][3]+=a3*Tw0.w;
            acc[3][4]+=a3*Tw1.x; acc[3][5]+=a3*Tw1.y; acc[3][6]+=a3*Tw1.z; acc[3][7]+=a3*Tw1.w;
        }
        float* srow = g_s + (size_t)c*S3 + (size_t)(d0+p)*4096;
        #pragma unroll
        for(int i=0;i<4;i++){
            int h = hg*4+i;
            float4* q = (float4*)(srow + h*64 + wg*8);
            float4 s0 = q[0], s1 = q[1];
            s0.x+=acc[i][0]; s0.y+=acc[i][1]; s0.z+=acc[i][2]; s0.w+=acc[i][3];
            s1.x+=acc[i][4]; s1.y+=acc[i][5]; s1.z+=acc[i][6]; s1.w+=acc[i][7];
            q[0]=s0; q[1]=s1;
            ssum += s0.x+s0.y+s0.z+s0.w + s1.x+s1.y+s1.z+s1.w;
            sq   += s0.x*s0.x+s0.y*s0.y+s0.z*s0.z+s0.w*s0.w
                  + s1.x*s1.x+s1.y*s1.y+s1.z*s1.z+s1.w*s1.w;
        }
    }
    #pragma unroll
    for(int o=16;o;o>>=1){ ssum += __shfl_xor_sync(0xffffffffu,ssum,o);
                           sq   += __shfl_xor_sync(0xffffffffu,sq,o); }
    int wp = threadIdx.x & 31, warp = threadIdx.x >> 5;
    if(wp==0){ redS[warp]=ssum; redQ[warp]=sq; }
    __syncthreads();
    if(threadIdx.x==0){
        float S = redS[0]+redS[1]+redS[2]+redS[3];
        float Q = redQ[0]+redQ[1]+redQ[2]+redQ[3];
        int g = c>>3;
        atomicAdd(&g_gn[g*2],   (double)S);
        atomicAdd(&g_gn[g*2+1], (double)Q);
    }
}

__global__ void gn_final_k(){
    int g = threadIdx.x;
    float mu_f=0.f, rs_f=0.f;
    if(g<8){
        double n = 8.0*(double)S3;
        double mu = g_gn[g*2]/n;
        double var = g_gn[g*2+1]/n - mu*mu;
        mu_f = (float)mu; rs_f = (float)(1.0/sqrt(var + 1e-5));
    }
    __syncthreads();
    if(g<8){ g_gnf[g*2]=mu_f; g_gnf[g*2+1]=rs_f; }
    if(g<16) g_gn[g]=0.0;
}

// ---------------- GN-apply + GELU + FiLM + conv(next layer) (R4 form) ----------------
__global__ void __launch_bounds__(256) gn_apply_conv_k(const float* __restrict__ gg, const float* __restrict__ gb,
        int l, const float* __restrict__ cw, const float* __restrict__ cb){
    int s0 = blockIdx.x*128;
    __shared__ float vsh[64][128];
    __shared__ float wshT[64][68];
    int s = threadIdx.x & 127, chalf = threadIdx.x >> 7;
    for(int i=threadIdx.x;i<4096;i+=256) wshT[i&63][i>>6] = cw[i];
    #pragma unroll
    for(int i=0;i<32;i++){
        int cc = i*2 + chalf;
        int g = cc>>3;
        float xv = (g_s[(size_t)cc*S3+s0+s]-g_gnf[g*2])*g_gnf[g*2+1]*__ldg(&gg[cc]) + __ldg(&gb[cc]);
        float y = gelu_f(xv);
        float v = y*(1.f+g_film[(l*64+cc)*2]) + g_film[(l*64+cc)*2+1];
        vsh[cc][s] = v;
        g_v[(size_t)cc*S3+s0+s] = v;
    }
    __syncthreads();
    int o0 = (threadIdx.x>>5)*8, si = (threadIdx.x&31)*4;
    float acc[8][4];
    #pragma unroll
    for(int a=0;a<8;a++){ acc[a][0]=0.f;acc[a][1]=0.f;acc[a][2]=0.f;acc[a][3]=0.f; }
    for(int k=0;k<64;k++){
        float4 v4 = *(const float4*)&vsh[k][si];
        float4 wa = *(const float4*)&wshT[k][o0];
        float4 wb = *(const float4*)&wshT[k][o0+4];
        acc[0][0]+=wa.x*v4.x; acc[0][1]+=wa.x*v4.y; acc[0][2]+=wa.x*v4.z; acc[0][3]+=wa.x*v4.w;
        acc[1][0]+=wa.y*v4.x; acc[1][1]+=wa.y*v4.y; acc[1][2]+=wa.y*v4.z; acc[1][3]+=wa.y*v4.w;
        acc[2][0]+=wa.z*v4.x; acc[2][1]+=wa.z*v4.y; acc[2][2]+=wa.z*v4.z; acc[2][3]+=wa.z*v4.w;
        acc[3][0]+=wa.w*v4.x; acc[3][1]+=wa.w*v4.y; acc[3][2]+=wa.w*v4.z; acc[3][3]+=wa.w*v4.w;
        acc[4][0]+=wb.x*v4.x; acc[4][1]+=wb.x*v4.y; acc[4][2]+=wb.x*v4.z; acc[4][3]+=wb.x*v4.w;
        acc[5][0]+=wb.y*v4.x; acc[5][1]+=wb.y*v4.y; acc[5][2]+=wb.y*v4.z; acc[5][3]+=wb.y*v4.w;
        acc[6][0]+=wb.z*v4.x; acc[6][1]+=wb.z*v4.y; acc[6][2]+=wb.z*v4.z; acc[6][3]+=wb.z*v4.w;
        acc[7][0]+=wb.w*v4.x; acc[7][1]+=wb.w*v4.y; acc[7][2]+=wb.w*v4.z; acc[7][3]+=wb.w*v4.w;
    }
    #pragma unroll
    for(int oi=0;oi<8;oi++){
        float bb = __ldg(&cb[o0+oi]);
        *(float4*)&g_s[(size_t)(o0+oi)*S3 + s0 + si] =
            make_float4(acc[oi][0]+bb, acc[oi][1]+bb, acc[oi][2]+bb, acc[oi][3]+bb);
    }
}

// ---------------- last layer: GN-apply + FiLM + p1 + GELU + p2 (R4 form) ----------------
__global__ void __launch_bounds__(256) gn_apply_head_k(const float* __restrict__ gg, const float* __restrict__ gb,
        int l, const float* __restrict__ w1, const float* __restrict__ b1,
        const float* __restrict__ w2, const float* __restrict__ b2, float* __restrict__ out){
    int s0 = blockIdx.x*64;
    __shared__ float vsh[64][64];
    __shared__ float wshT[64][68];
    __shared__ float w2s[3][128];
    __shared__ float red[16][3][64];
    int s = threadIdx.x & 63, cq = threadIdx.x >> 6;
    for(int i=threadIdx.x;i<384;i+=256){ int j=i>>7, o=i&127; w2s[j][o]=w2[j*128+o]; }
    #pragma unroll
    for(int i=0;i<16;i++){
        int cc = i*4 + cq;
        int g = cc>>3;
        float xv = (g_s[(size_t)cc*S3+s0+s]-g_gnf[g*2])*g_gnf[g*2+1]*__ldg(&gg[cc]) + __ldg(&gb[cc]);
        float y = gelu_f(xv);
        vsh[cc][s] = y*(1.f+g_film[(l*64+cc)*2]) + g_film[(l*64+cc)*2+1];
    }
    int og = threadIdx.x >> 4, sg = threadIdx.x & 15;
    int o0 = og*4, si = sg*4;
    float p[3][4];
    #pragma unroll
    for(int j=0;j<3;j++){ p[j][0]=0.f;p[j][1]=0.f;p[j][2]=0.f;p[j][3]=0.f; }
    for(int half=0; half<2; half++){
        __syncthreads();
        for(int i=threadIdx.x;i<4096;i+=256){ int o=i>>6,k=i&63; wshT[k][o]=w1[(half*64+o)*64+k]; }
        __syncthreads();
        float acc[4][4];
        #pragma unroll
        for(int a=0;a<4;a++){ acc[a][0]=0.f;acc[a][1]=0.f;acc[a][2]=0.f;acc[a][3]=0.f; }
        for(int k=0;k<64;k++){
            float4 v4 = *(const float4*)&vsh[k][si];
            float4 wv = *(const float4*)&wshT[k][o0];
            acc[0][0]+=wv.x*v4.x; acc[0][1]+=wv.x*v4.y; acc[0][2]+=wv.x*v4.z; acc[0][3]+=wv.x*v4.w;
            acc[1][0]+=wv.y*v4.x; acc[1][1]+=wv.y*v4.y; acc[1][2]+=wv.y*v4.z; acc[1][3]+=wv.y*v4.w;
            acc[2][0]+=wv.z*v4.x; acc[2][1]+=wv.z*v4.y; acc[2][2]+=wv.z*v4.z; acc[2][3]+=wv.z*v4.w;
            acc[3][0]+=wv.w*v4.x; acc[3][1]+=wv.w*v4.y; acc[3][2]+=wv.w*v4.z; acc[3][3]+=wv.w*v4.w;
        }
        #pragma unroll
        for(int oi=0;oi<4;oi++){
            int o = half*64 + o0 + oi;
            float bb = __ldg(&b1[o]);
            #pragma unroll
            for(int sx=0;sx<4;sx++){
                float u = gelu_f(acc[oi][sx] + bb);
                p[0][sx] += u*w2s[0][o];
                p[1][sx] += u*w2s[1][o];
                p[2][sx] += u*w2s[2][o];
            }
        }
    }
    #pragma unroll
    for(int j=0;j<3;j++){
        red[og][j][si+0]=p[j][0]; red[og][j][si+1]=p[j][1];
        red[og][j][si+2]=p[j][2]; red[og][j][si+3]=p[j][3];
    }
    __syncthreads();
    if(threadIdx.x < 64){
        int ss = threadIdx.x;
        #pragma unroll
        for(int j=0;j<3;j++){
            float acc = __ldg(&b2[j]);
            #pragma unroll
            for(int gq=0;gq<16;gq++) acc += red[gq][j][ss];
            out[(size_t)j*S3 + s0 + ss] = acc;
        }
    }
}

// ---------------- launch ----------------
extern "C" void kernel_launch(void* const* d_in, const int* in_sizes, int n_in,
                              void* d_out, int out_size){
    const float* x      = (const float*)d_in[0];
    const float* latent = (const float*)d_in[1];
    const float* lift_w = (const float*)d_in[2];
    const float* lift_b = (const float*)d_in[3];
    const float* sc_w1  = (const float*)d_in[4];
    const float* sc_w2  = (const float*)d_in[5];
    const float* sc_w3  = (const float*)d_in[6];
    const float* sc_w4  = (const float*)d_in[7];
    const float* conv_w = (const float*)d_in[8];
    const float* conv_b = (const float*)d_in[9];
    const float* gn_g   = (const float*)d_in[10];
    const float* gn_b   = (const float*)d_in[11];
    const float* p1_w   = (const float*)d_in[12];
    const float* p1_b   = (const float*)d_in[13];
    const float* p2_w   = (const float*)d_in[14];
    const float* p2_b   = (const float*)d_in[15];
    const float* c1_w   = (const float*)d_in[16];
    const float* c1_b   = (const float*)d_in[17];
    const float* c2_w   = (const float*)d_in[18];
    const float* c2_b   = (const float*)d_in[19];
    float* out = (float*)d_out;

    static int smem_set = 0;
    if(!smem_set){
        cudaFuncSetAttribute(fwdWH_k, cudaFuncAttributeMaxDynamicSharedMemorySize, FWD_SMEM);
        smem_set = 1;
    }

    // Order keeps the ncu capture landing on fwdWH_k (4th launch).
    init_tables_k<<<6,256>>>();
    film1_k<<<128,256>>>(latent, c1_w, c1_b);
    lift_conv_k<<<2048,256>>>(x, lift_w, lift_b, conv_w, conv_b);

    const size_t WOFF = (size_t)64*64*12*12*12*2;
    for(int l=0;l<3;l++){
        fwdWH_k<<<dim3(16,64),256,FWD_SMEM>>>();
        if(l==0) film2_k<<<48,256>>>(c2_w, c2_b);
        fwdD_k<<<dim3(24,64),128>>>();
        mix_k<<<dim3(108,8),256>>>(sc_w1 + l*WOFF, sc_w2 + l*WOFF,
                                   sc_w3 + l*WOFF, sc_w4 + l*WOFF);
        invD_k<<<dim3(24,64),128>>>();
        invHW_gn_k<<<dim3(32,64),128>>>();
        gn_final_k<<<1,32>>>();
        if(l<2)
            gn_apply_conv_k<<<2048,256>>>(gn_g + l*64, gn_b + l*64, l,
                                          conv_w + (l+1)*4096, conv_b + (l+1)*64);
        else
            gn_apply_head_k<<<4096,256>>>(gn_g + l*64, gn_b + l*64, l,
                                          p1_w, p1_b, p2_w, p2_b, out);
    }
}

// round 14
// speedup vs baseline: 1.0692x; 1.0190x over previous
#include <cuda_runtime.h>
#include <math.h>

#define S3 262144        // 64^3
#define NMODE 6912       // 4 corners * 1728

// ---------------- scratch ----------------
__device__ float  g_v[64*S3];
__device__ float  g_s[64*S3];
__device__ float2 g_B[64*64*288];
__device__ float2 g_X[64*NMODE];   // corner-major: c*NMODE + corner*1728 + cmode
__device__ float2 g_Y[64*NMODE];
__device__ float  g_h1[1024];
__device__ float  g_film[384];
__device__ double g_gn[16];
__device__ float  g_gnf[16];
__device__ __align__(16) float2 tw_fWt[64*12];   // [w][kw]  fwd W twiddle (c,-s), transposed
__device__ __align__(16) float2 tw_iW[12*64];    // [kw][w]  inv W twiddle * alpha/64^3 (c,s)
__device__ __align__(16) float2 tw_fDHt[64*24];  // [x][j]   fwd D/H twiddle (c,-s), transposed
__device__ __align__(16) float2 tw_iDH[24*64];   // [j][x]   inv D/H twiddle (c,s)

__device__ __forceinline__ float gelu_f(float x){
    return 0.5f*x*(1.0f + erff(x*0.7071067811865476f));
}

#define CMAC(acc, a, t) { acc.x += a.x*t.x - a.y*t.y; acc.y += a.x*t.y + a.y*t.x; }

// ---------------- tables ----------------
__global__ void init_tables_k(){
    int t = blockIdx.x*blockDim.x + threadIdx.x;
    const double w0 = 6.283185307179586476925286766559/64.0;
    if(t < 768){
        int kw = t>>6, w = t&63;
        double s,c; sincos(w0*(double)(kw*w), &s, &c);
        tw_fWt[w*12+kw] = make_float2((float)c, (float)(-s));
        double al = (kw==0 ? 1.0 : 2.0) / 262144.0;
        tw_iW[kw*64+w] = make_float2((float)(al*c), (float)(al*s));
    }
    if(t < 1536){
        int j = t>>6, x = t&63;
        int bin = (j<12) ? j : (j+40);
        double s,c; sincos(w0*(double)(bin*x), &s, &c);
        tw_fDHt[x*24+j] = make_float2((float)c, (float)(-s));
        tw_iDH[j*64+x]  = make_float2((float)c, (float)( s));
    }
    if(t < 16) g_gn[t] = 0.0;
}

// ---------------- FiLM ----------------
__global__ void film1_k(const float* __restrict__ latent, const float* __restrict__ w,
                        const float* __restrict__ b){
    int wid  = (blockIdx.x*blockDim.x + threadIdx.x) >> 5;
    int lane = threadIdx.x & 31;
    if(wid >= 1024) return;
    const float* wr = w + wid*512;
    float acc = 0.f;
    for(int k=lane;k<512;k+=32) acc += latent[k]*wr[k];
    #pragma unroll
    for(int o=16;o;o>>=1) acc += __shfl_xor_sync(0xffffffffu, acc, o);
    if(lane==0) g_h1[wid] = gelu_f(acc + b[wid]);
}
__global__ void film2_k(const float* __restrict__ w, const float* __restrict__ b){
    int wid  = (blockIdx.x*blockDim.x + threadIdx.x) >> 5;
    int lane = threadIdx.x & 31;
    if(wid >= 384) return;
    const float* wr = w + wid*1024;
    float acc = 0.f;
    for(int k=lane;k<1024;k+=32) acc += g_h1[k]*wr[k];
    #pragma unroll
    for(int o=16;o;o>>=1) acc += __shfl_xor_sync(0xffffffffu, acc, o);
    if(lane==0) g_film[wid] = acc + b[wid];
}

// ---------------- lift + conv(layer0), register-tiled (R4 form) ----------------
__global__ void __launch_bounds__(256) lift_conv_k(const float* __restrict__ x,
        const float* __restrict__ lw, const float* __restrict__ lb,
        const float* __restrict__ cw, const float* __restrict__ cb){
    int s0 = blockIdx.x*128;
    __shared__ float vsh[64][128];
    __shared__ float wshT[64][68];
    int s = threadIdx.x & 127, chalf = threadIdx.x >> 7;
    float x0 = __ldg(&x[s0+s]),        x1 = __ldg(&x[S3+s0+s]);
    float x2 = __ldg(&x[2*S3+s0+s]),   x3 = __ldg(&x[3*S3+s0+s]);
    for(int i=threadIdx.x;i<4096;i+=256) wshT[i&63][i>>6] = cw[i];
    #pragma unroll
    for(int i=0;i<32;i++){
        int cc = i*2 + chalf;
        float v = __ldg(&lb[cc]) + __ldg(&lw[cc*4+0])*x0 + __ldg(&lw[cc*4+1])*x1
                                 + __ldg(&lw[cc*4+2])*x2 + __ldg(&lw[cc*4+3])*x3;
        vsh[cc][s] = v;
        g_v[(size_t)cc*S3 + s0 + s] = v;
    }
    __syncthreads();
    int o0 = (threadIdx.x>>5)*8, si = (threadIdx.x&31)*4;
    float acc[8][4];
    #pragma unroll
    for(int a=0;a<8;a++){ acc[a][0]=0.f;acc[a][1]=0.f;acc[a][2]=0.f;acc[a][3]=0.f; }
    for(int k=0;k<64;k++){
        float4 v4 = *(const float4*)&vsh[k][si];
        float4 wa = *(const float4*)&wshT[k][o0];
        float4 wb = *(const float4*)&wshT[k][o0+4];
        acc[0][0]+=wa.x*v4.x; acc[0][1]+=wa.x*v4.y; acc[0][2]+=wa.x*v4.z; acc[0][3]+=wa.x*v4.w;
        acc[1][0]+=wa.y*v4.x; acc[1][1]+=wa.y*v4.y; acc[1][2]+=wa.y*v4.z; acc[1][3]+=wa.y*v4.w;
        acc[2][0]+=wa.z*v4.x; acc[2][1]+=wa.z*v4.y; acc[2][2]+=wa.z*v4.z; acc[2][3]+=wa.z*v4.w;
        acc[3][0]+=wa.w*v4.x; acc[3][1]+=wa.w*v4.y; acc[3][2]+=wa.w*v4.z; acc[3][3]+=wa.w*v4.w;
        acc[4][0]+=wb.x*v4.x; acc[4][1]+=wb.x*v4.y; acc[4][2]+=wb.x*v4.z; acc[4][3]+=wb.x*v4.w;
        acc[5][0]+=wb.y*v4.x; acc[5][1]+=wb.y*v4.y; acc[5][2]+=wb.y*v4.z; acc[5][3]+=wb.y*v4.w;
        acc[6][0]+=wb.z*v4.x; acc[6][1]+=wb.z*v4.y; acc[6][2]+=wb.z*v4.z; acc[6][3]+=wb.z*v4.w;
        acc[7][0]+=wb.w*v4.x; acc[7][1]+=wb.w*v4.y; acc[7][2]+=wb.w*v4.z; acc[7][3]+=wb.w*v4.w;
    }
    #pragma unroll
    for(int oi=0;oi<8;oi++){
        float bb = __ldg(&cb[o0+oi]);
        *(float4*)&g_s[(size_t)(o0+oi)*S3 + s0 + si] =
            make_float4(acc[oi][0]+bb, acc[oi][1]+bb, acc[oi][2]+bb, acc[oi][3]+bb);
    }
}

// ---------------- fused forward DFT: H first, then W (no transpose) ----------------
// 2 d-planes/block, 256 threads.
// dyn smem: vsh[2][64][65] f (33280B) + Ash[2][64][14] f2 (14336B) + twWs[64][12] f2 (6144B)
#define FWD_SMEM (33280 + 14336 + 6144)

__global__ void __launch_bounds__(256) fwdWH_k(){
    extern __shared__ __align__(16) float sm[];
    float*  vsh  = sm;                       // [p][h][65]
    float2* Ash  = (float2*)(sm + 8320);     // [p][h][14]  ([h][kw] complex)
    float2* twWs = (float2*)(sm + 8320 + 3584); // [w][12]
    int d0 = blockIdx.x*2, c = blockIdx.y;

    for(int i=threadIdx.x;i<2048;i+=256){
        int p = i>>10, j = i&1023;
        float4 v4 = *(const float4*)(g_v + (size_t)(c*64+d0+p)*4096 + j*4);
        int h = j>>4, w4 = (j&15)*4;
        float* row = vsh + (size_t)(p*64+h)*65 + w4;
        row[0]=v4.x; row[1]=v4.y; row[2]=v4.z; row[3]=v4.w;
    }
    for(int i=threadIdx.x;i<768;i+=256) twWs[i] = tw_fWt[i];
    __syncthreads();

    // stage 1: H-DFT (contract h). thread = (p, h-pair, kw-quarter): 6 complex acc
    {
        int r = threadIdx.x & 127, p = threadIdx.x >> 7;
        int h0 = (r&31)*2, jq = (r>>5)*6;   // jq: 6 jh per thread? no -> see below
        // NOTE: stage 1 contracts h producing jh bins; thread owns (p, w-pair?).
        // Correct mapping: contract h for fixed w. Thread = (p, w-pair, jh-quarter).
        int w0 = h0;            // reuse: w0 = (r&31)*2  (two w columns)
        int jh0 = (r>>5)*6;     // 6 jh per thread
        float re[6][2], im[6][2];
        #pragma unroll
        for(int j=0;j<6;j++){ re[j][0]=re[j][1]=0.f; im[j][0]=im[j][1]=0.f; }
        const float* base = vsh + (size_t)p*64*65;
        #pragma unroll 2
        for(int h=0;h<64;h++){
            float v0 = base[h*65 + w0];
            float v1 = base[h*65 + w0+1];
            const float4* tp = (const float4*)(tw_fDHt + h*24 + jh0);
            float4 t0 = __ldg(tp), t1 = __ldg(tp+1), t2 = __ldg(tp+2);
            float tc[6] = {t0.x,t0.z,t1.x,t1.z,t2.x,t2.z};
            float ts[6] = {t0.y,t0.w,t1.y,t1.w,t2.y,t2.w};
            #pragma unroll
            for(int j=0;j<6;j++){
                re[j][0]+=v0*tc[j]; im[j][0]+=v0*ts[j];
                re[j][1]+=v1*tc[j]; im[j][1]+=v1*ts[j];
            }
        }
        // write A[jh][w] into vsh region? Need (jh, w) complex 24x64 per plane.
        // Store into Ash2 region: reuse vsh as scratch is unsafe (still needed? no - h fully consumed).
        // Write to a [jh][w] complex layout placed in the vsh area after sync.
        __syncthreads();
        float2* AW = (float2*)vsh;            // [p][jh][w+pad66] complex? size: 2*24*66*8=25344 < 33280 OK
        #pragma unroll
        for(int j=0;j<6;j++){
            AW[((size_t)p*24 + jh0+j)*66 + w0]   = make_float2(re[j][0], im[j][0]);
            AW[((size_t)p*24 + jh0+j)*66 + w0+1] = make_float2(re[j][1], im[j][1]);
        }
    }
    __syncthreads();

    // stage 2: W-DFT (contract w). thread (of 192) = (p, jh, kw-group of 3)
    if(threadIdx.x < 192){
        int idx = threadIdx.x;
        int p = idx/96, r2 = idx%96, jh = r2%24, kg = r2/24;
        int kw0 = kg*3;
        const float2* AW = (const float2*)vsh;
        const float2* arow = AW + ((size_t)p*24 + jh)*66;
        float2 b0={0,0}, b1={0,0}, b2={0,0};
        #pragma unroll 2
        for(int w=0;w<64;w++){
            float2 a  = arow[w];
            float2 t0 = twWs[w*12+kw0];
            float2 t1 = twWs[w*12+kw0+1];
            float2 t2 = twWs[w*12+kw0+2];
            CMAC(b0,a,t0); CMAC(b1,a,t1); CMAC(b2,a,t2);
        }
        float2* dst = g_B + (size_t)(c*64+d0+p)*288 + jh*12 + kw0;
        dst[0]=b0; dst[1]=b1; dst[2]=b2;
    }
}

// ---------------- forward DFT over D (stores corner-major) ----------------
__global__ void __launch_bounds__(128) fwdD_k(){
    int jh = blockIdx.x, c = blockIdx.y;
    __shared__ float2 Bsh[64][12];
    for(int i=threadIdx.x;i<768;i+=128){
        int d = i/12, kw = i - d*12;
        Bsh[d][kw] = g_B[(size_t)(c*64+d)*288 + jh*12 + kw];
    }
    __syncthreads();
    if(threadIdx.x < 96){
        int kw = threadIdx.x % 12, jd0 = (threadIdx.x/12)*3;
        float2 b0={0,0},b1={0,0},b2={0,0};
        for(int d=0;d<64;d++){
            float2 a = Bsh[d][kw];
            float2 t0 = __ldg(&tw_fDHt[d*24+jd0]);
            float2 t1 = __ldg(&tw_fDHt[d*24+jd0+1]);
            float2 t2 = __ldg(&tw_fDHt[d*24+jd0+2]);
            CMAC(b0,a,t0); CMAC(b1,a,t1); CMAC(b2,a,t2);
        }
        int jhm = jh % 12, cbase = (jh>=12) ? 2 : 0;
        #pragma unroll
        for(int r=0;r<3;r++){
            int jd = jd0 + r;
            int corner = cbase + (jd>=12 ? 1 : 0);
            int cmode = ((jd%12)*12 + jhm)*12 + kw;
            float2 b = (r==0)?b0:(r==1)?b1:b2;
            g_X[(size_t)c*NMODE + corner*1728 + cmode] = b;
        }
    }
}

// ---------------- per-mode channel mix: float4 streaming ----------------
__global__ void __launch_bounds__(256) mix_k(const float* __restrict__ w1, const float* __restrict__ w2,
                                             const float* __restrict__ w3, const float* __restrict__ w4){
    int corner = blockIdx.x / 27;
    int c0 = (blockIdx.x - corner*27) * 64;
    const float* wbase = (corner==0)?w1:(corner==1)?w2:(corner==2)?w3:w4;
    __shared__ float2 xs[64][64];
    int tx = threadIdx.x & 31, ty = threadIdx.x >> 5;
    for(int i=ty; i<64; i+=8)
        ((float4*)xs[i])[tx] = *(const float4*)(&g_X[(size_t)i*NMODE + corner*1728 + c0 + tx*2]);
    __syncthreads();
    int o = blockIdx.y*8 + ty;
    const float* Wp = wbase + ((size_t)o*1728 + c0 + tx*2)*2;
    float re0=0.f,im0=0.f,re1=0.f,im1=0.f;
    #pragma unroll 8
    for(int i=0;i<64;i++){
        float4 wv = *(const float4*)(Wp + (size_t)i*221184);
        float4 xx = ((const float4*)xs[i])[tx];
        re0 += xx.x*wv.x - xx.y*wv.y; im0 += xx.x*wv.y + xx.y*wv.x;
        re1 += xx.z*wv.z - xx.w*wv.w; im1 += xx.z*wv.w + xx.w*wv.z;
    }
    *(float4*)(&g_Y[(size_t)o*NMODE + corner*1728 + c0 + tx*2]) = make_float4(re0,im0,re1,im1);
}

// ---------------- inverse DFT over D (reads corner-major) ----------------
__global__ void __launch_bounds__(128) invD_k(){
    int jh = blockIdx.x, c = blockIdx.y;
    __shared__ __align__(16) float2 Ysh[24][12];
    int jhm = jh % 12, cbase = (jh>=12) ? 2 : 0;
    for(int i=threadIdx.x;i<288;i+=128){
        int jd = i/12, kw = i - jd*12;
        int corner = cbase + (jd>=12 ? 1 : 0);
        int cmode = ((jd%12)*12 + jhm)*12 + kw;
        Ysh[jd][kw] = g_Y[(size_t)c*NMODE + corner*1728 + cmode];
    }
    __syncthreads();
    int d = threadIdx.x & 63, kw0 = (threadIdx.x>>6)*6;
    float2 a0={0,0},a1={0,0},a2={0,0},a3={0,0},a4={0,0},a5={0,0};
    for(int jd=0;jd<24;jd++){
        float2 t = __ldg(&tw_iDH[jd*64+d]);
        const float4* yp = (const float4*)(&Ysh[jd][kw0]);
        float4 y0 = yp[0], y1 = yp[1], y2 = yp[2];
        float2 v;
        v = make_float2(y0.x,y0.y); CMAC(a0,v,t);
        v = make_float2(y0.z,y0.w); CMAC(a1,v,t);
        v = make_float2(y1.x,y1.y); CMAC(a2,v,t);
        v = make_float2(y1.z,y1.w); CMAC(a3,v,t);
        v = make_float2(y2.x,y2.y); CMAC(a4,v,t);
        v = make_float2(y2.z,y2.w); CMAC(a5,v,t);
    }
    float2* dst = g_B + (size_t)(c*64+d)*288 + jh*12 + kw0;
    dst[0]=a0; dst[1]=a1; dst[2]=a2; dst[3]=a3; dst[4]=a4; dst[5]=a5;
}

// ---------------- fused inverse H + W + residual add + GN stats, GEMM form ----------------
__global__ void __launch_bounds__(128) invHW_gn_k(){
    int d0 = blockIdx.x*2, c = blockIdx.y;
    __shared__ __align__(16) float2 Bsh[2][288];
    __shared__ __align__(16) float Ash[2][64][26];
    __shared__ __align__(16) float T2[24][68];
    __shared__ float redS[4], redQ[4];

    for(int i=threadIdx.x;i<576;i+=128){
        int p = (i>=288) ? 1 : 0;
        int idx = i - p*288;
        Bsh[p][idx] = g_B[(size_t)(c*64+d0+p)*288 + idx];
    }
    for(int i=threadIdx.x;i<1536;i+=128){
        int k = i>>6, w = i&63;
        float2 t = tw_iW[(k>>1)*64 + w];
        T2[k][w] = (k&1) ? -t.y : t.x;
    }
    __syncthreads();

    {
        int p = threadIdx.x>>6, u = threadIdx.x&63;
        int h0 = (u&31)*2, kw0 = (u>>5)*6;
        float are[2][6], aim[2][6];
        #pragma unroll
        for(int i=0;i<2;i++)
            #pragma unroll
            for(int j=0;j<6;j++){ are[i][j]=0.f; aim[i][j]=0.f; }
        for(int jh=0;jh<24;jh++){
            float4 tt = __ldg((const float4*)&tw_iDH[jh*64+h0]);
            const float4* bp = (const float4*)&Bsh[p][jh*12+kw0];
            float4 b0 = bp[0], b1 = bp[1], b2 = bp[2];
            float br[6] = {b0.x, b0.z, b1.x, b1.z, b2.x, b2.z};
            float bi[6] = {b0.y, b0.w, b1.y, b1.w, b2.y, b2.w};
            #pragma unroll
            for(int j=0;j<6;j++){
                are[0][j] += br[j]*tt.x - bi[j]*tt.y;
                aim[0][j] += br[j]*tt.y + bi[j]*tt.x;
                are[1][j] += br[j]*tt.z - bi[j]*tt.w;
                aim[1][j] += br[j]*tt.w + bi[j]*tt.z;
            }
        }
        #pragma unroll
        for(int i=0;i<2;i++)
            #pragma unroll
            for(int j=0;j<6;j++){
                float* a = &Ash[p][h0+i][2*(kw0+j)];
                a[0]=are[i][j]; a[1]=aim[i][j];
            }
    }
    __syncthreads();

    int wg = threadIdx.x&7, hg = threadIdx.x>>3;
    float ssum=0.f, sq=0.f;
    for(int p=0;p<2;p++){
        float acc[4][8];
        #pragma unroll
        for(int i=0;i<4;i++)
            #pragma unroll
            for(int j=0;j<8;j++) acc[i][j]=0.f;
        for(int k=0;k<24;k++){
            float4 Tw0 = *(const float4*)&T2[k][wg*8];
            float4 Tw1 = *(const float4*)&T2[k][wg*8+4];
            float a0 = Ash[p][hg*4+0][k];
            float a1 = Ash[p][hg*4+1][k];
            float a2 = Ash[p][hg*4+2][k];
            float a3 = Ash[p][hg*4+3][k];
            acc[0][0]+=a0*Tw0.x; acc[0][1]+=a0*Tw0.y; acc[0][2]+=a0*Tw0.z; acc[0][3]+=a0*Tw0.w;
            acc[0][4]+=a0*Tw1.x; acc[0][5]+=a0*Tw1.y; acc[0][6]+=a0*Tw1.z; acc[0][7]+=a0*Tw1.w;
            acc[1][0]+=a1*Tw0.x; acc[1][1]+=a1*Tw0.y; acc[1][2]+=a1*Tw0.z; acc[1][3]+=a1*Tw0.w;
            acc[1][4]+=a1*Tw1.x; acc[1][5]+=a1*Tw1.y; acc[1][6]+=a1*Tw1.z; acc[1][7]+=a1*Tw1.w;
            acc[2][0]+=a2*Tw0.x; acc[2][1]+=a2*Tw0.y; acc[2][2]+=a2*Tw0.z; acc[2][3]+=a2*Tw0.w;
            acc[2][4]+=a2*Tw1.x; acc[2][5]+=a2*Tw1.y; acc[2][6]+=a2*Tw1.z; acc[2][7]+=a2*Tw1.w;
            acc[3][0]+=a3*Tw0.x; acc[3][1]+=a3*Tw0.y; acc[3][2]+=a3*Tw0.z; acc[3][3]+=a3*Tw0.w;
            acc[3][4]+=a3*Tw1.x; acc[3][5]+=a3*Tw1.y; acc[3][6]+=a3*Tw1.z; acc[3][7]+=a3*Tw1.w;
        }
        float* srow = g_s + (size_t)c*S3 + (size_t)(d0+p)*4096;
        #pragma unroll
        for(int i=0;i<4;i++){
            int h = hg*4+i;
            float4* q = (float4*)(srow + h*64 + wg*8);
            float4 s0 = q[0], s1 = q[1];
            s0.x+=acc[i][0]; s0.y+=acc[i][1]; s0.z+=acc[i][2]; s0.w+=acc[i][3];
            s1.x+=acc[i][4]; s1.y+=acc[i][5]; s1.z+=acc[i][6]; s1.w+=acc[i][7];
            q[0]=s0; q[1]=s1;
            ssum += s0.x+s0.y+s0.z+s0.w + s1.x+s1.y+s1.z+s1.w;
            sq   += s0.x*s0.x+s0.y*s0.y+s0.z*s0.z+s0.w*s0.w
                  + s1.x*s1.x+s1.y*s1.y+s1.z*s1.z+s1.w*s1.w;
        }
    }
    #pragma unroll
    for(int o=16;o;o>>=1){ ssum += __shfl_xor_sync(0xffffffffu,ssum,o);
                           sq   += __shfl_xor_sync(0xffffffffu,sq,o); }
    int wp = threadIdx.x & 31, warp = threadIdx.x >> 5;
    if(wp==0){ redS[warp]=ssum; redQ[warp]=sq; }
    __syncthreads();
    if(threadIdx.x==0){
        float S = redS[0]+redS[1]+redS[2]+redS[3];
        float Q = redQ[0]+redQ[1]+redQ[2]+redQ[3];
        int g = c>>3;
        atomicAdd(&g_gn[g*2],   (double)S);
        atomicAdd(&g_gn[g*2+1], (double)Q);
    }
}

__global__ void gn_final_k(){
    int g = threadIdx.x;
    float mu_f=0.f, rs_f=0.f;
    if(g<8){
        double n = 8.0*(double)S3;
        double mu = g_gn[g*2]/n;
        double var = g_gn[g*2+1]/n - mu*mu;
        mu_f = (float)mu; rs_f = (float)(1.0/sqrt(var + 1e-5));
    }
    __syncthreads();
    if(g<8){ g_gnf[g*2]=mu_f; g_gnf[g*2+1]=rs_f; }
    if(g<16) g_gn[g]=0.0;
}

// ---------------- GN-apply + GELU + FiLM + conv(next layer) (R4 form) ----------------
__global__ void __launch_bounds__(256) gn_apply_conv_k(const float* __restrict__ gg, const float* __restrict__ gb,
        int l, const float* __restrict__ cw, const float* __restrict__ cb){
    int s0 = blockIdx.x*128;
    __shared__ float vsh[64][128];
    __shared__ float wshT[64][68];
    int s = threadIdx.x & 127, chalf = threadIdx.x >> 7;
    for(int i=threadIdx.x;i<4096;i+=256) wshT[i&63][i>>6] = cw[i];
    #pragma unroll
    for(int i=0;i<32;i++){
        int cc = i*2 + chalf;
        int g = cc>>3;
        float xv = (g_s[(size_t)cc*S3+s0+s]-g_gnf[g*2])*g_gnf[g*2+1]*__ldg(&gg[cc]) + __ldg(&gb[cc]);
        float y = gelu_f(xv);
        float v = y*(1.f+g_film[(l*64+cc)*2]) + g_film[(l*64+cc)*2+1];
        vsh[cc][s] = v;
        g_v[(size_t)cc*S3+s0+s] = v;
    }
    __syncthreads();
    int o0 = (threadIdx.x>>5)*8, si = (threadIdx.x&31)*4;
    float acc[8][4];
    #pragma unroll
    for(int a=0;a<8;a++){ acc[a][0]=0.f;acc[a][1]=0.f;acc[a][2]=0.f;acc[a][3]=0.f; }
    for(int k=0;k<64;k++){
        float4 v4 = *(const float4*)&vsh[k][si];
        float4 wa = *(const float4*)&wshT[k][o0];
        float4 wb = *(const float4*)&wshT[k][o0+4];
        acc[0][0]+=wa.x*v4.x; acc[0][1]+=wa.x*v4.y; acc[0][2]+=wa.x*v4.z; acc[0][3]+=wa.x*v4.w;
        acc[1][0]+=wa.y*v4.x; acc[1][1]+=wa.y*v4.y; acc[1][2]+=wa.y*v4.z; acc[1][3]+=wa.y*v4.w;
        acc[2][0]+=wa.z*v4.x; acc[2][1]+=wa.z*v4.y; acc[2][2]+=wa.z*v4.z; acc[2][3]+=wa.z*v4.w;
        acc[3][0]+=wa.w*v4.x; acc[3][1]+=wa.w*v4.y; acc[3][2]+=wa.w*v4.z; acc[3][3]+=wa.w*v4.w;
        acc[4][0]+=wb.x*v4.x; acc[4][1]+=wb.x*v4.y; acc[4][2]+=wb.x*v4.z; acc[4][3]+=wb.x*v4.w;
        acc[5][0]+=wb.y*v4.x; acc[5][1]+=wb.y*v4.y; acc[5][2]+=wb.y*v4.z; acc[5][3]+=wb.y*v4.w;
        acc[6][0]+=wb.z*v4.x; acc[6][1]+=wb.z*v4.y; acc[6][2]+=wb.z*v4.z; acc[6][3]+=wb.z*v4.w;
        acc[7][0]+=wb.w*v4.x; acc[7][1]+=wb.w*v4.y; acc[7][2]+=wb.w*v4.z; acc[7][3]+=wb.w*v4.w;
    }
    #pragma unroll
    for(int oi=0;oi<8;oi++){
        float bb = __ldg(&cb[o0+oi]);
        *(float4*)&g_s[(size_t)(o0+oi)*S3 + s0 + si] =
            make_float4(acc[oi][0]+bb, acc[oi][1]+bb, acc[oi][2]+bb, acc[oi][3]+bb);
    }
}

// ---------------- last layer: GN-apply + FiLM + p1 + GELU + p2 (R4 form) ----------------
__global__ void __launch_bounds__(256) gn_apply_head_k(const float* __restrict__ gg, const float* __restrict__ gb,
        int l, const float* __restrict__ w1, const float* __restrict__ b1,
        const float* __restrict__ w2, const float* __restrict__ b2, float* __restrict__ out){
    int s0 = blockIdx.x*64;
    __shared__ float vsh[64][64];
    __shared__ float wshT[64][68];
    __shared__ float w2s[3][128];
    __shared__ float red[16][3][64];
    int s = threadIdx.x & 63, cq = threadIdx.x >> 6;
    for(int i=threadIdx.x;i<384;i+=256){ int j=i>>7, o=i&127; w2s[j][o]=w2[j*128+o]; }
    #pragma unroll
    for(int i=0;i<16;i++){
        int cc = i*4 + cq;
        int g = cc>>3;
        float xv = (g_s[(size_t)cc*S3+s0+s]-g_gnf[g*2])*g_gnf[g*2+1]*__ldg(&gg[cc]) + __ldg(&gb[cc]);
        float y = gelu_f(xv);
        vsh[cc][s] = y*(1.f+g_film[(l*64+cc)*2]) + g_film[(l*64+cc)*2+1];
    }
    int og = threadIdx.x >> 4, sg = threadIdx.x & 15;
    int o0 = og*4, si = sg*4;
    float p[3][4];
    #pragma unroll
    for(int j=0;j<3;j++){ p[j][0]=0.f;p[j][1]=0.f;p[j][2]=0.f;p[j][3]=0.f; }
    for(int half=0; half<2; half++){
        __syncthreads();
        for(int i=threadIdx.x;i<4096;i+=256){ int o=i>>6,k=i&63; wshT[k][o]=w1[(half*64+o)*64+k]; }
        __syncthreads();
        float acc[4][4];
        #pragma unroll
        for(int a=0;a<4;a++){ acc[a][0]=0.f;acc[a][1]=0.f;acc[a][2]=0.f;acc[a][3]=0.f; }
        for(int k=0;k<64;k++){
            float4 v4 = *(const float4*)&vsh[k][si];
            float4 wv = *(const float4*)&wshT[k][o0];
            acc[0][0]+=wv.x*v4.x; acc[0][1]+=wv.x*v4.y; acc[0][2]+=wv.x*v4.z; acc[0][3]+=wv.x*v4.w;
            acc[1][0]+=wv.y*v4.x; acc[1][1]+=wv.y*v4.y; acc[1][2]+=wv.y*v4.z; acc[1][3]+=wv.y*v4.w;
            acc[2][0]+=wv.z*v4.x; acc[2][1]+=wv.z*v4.y; acc[2][2]+=wv.z*v4.z; acc[2][3]+=wv.z*v4.w;
            acc[3][0]+=wv.w*v4.x; acc[3][1]+=wv.w*v4.y; acc[3][2]+=wv.w*v4.z; acc[3][3]+=wv.w*v4.w;
        }
        #pragma unroll
        for(int oi=0;oi<4;oi++){
            int o = half*64 + o0 + oi;
            float bb = __ldg(&b1[o]);
            #pragma unroll
            for(int sx=0;sx<4;sx++){
                float u = gelu_f(acc[oi][sx] + bb);
                p[0][sx] += u*w2s[0][o];
                p[1][sx] += u*w2s[1][o];
                p[2][sx] += u*w2s[2][o];
            }
        }
    }
    #pragma unroll
    for(int j=0;j<3;j++){
        red[og][j][si+0]=p[j][0]; red[og][j][si+1]=p[j][1];
        red[og][j][si+2]=p[j][2]; red[og][j][si+3]=p[j][3];
    }
    __syncthreads();
    if(threadIdx.x < 64){
        int ss = threadIdx.x;
        #pragma unroll
        for(int j=0;j<3;j++){
            float acc = __ldg(&b2[j]);
            #pragma unroll
            for(int gq=0;gq<16;gq++) acc += red[gq][j][ss];
            out[(size_t)j*S3 + s0 + ss] = acc;
        }
    }
}

// ---------------- launch ----------------
extern "C" void kernel_launch(void* const* d_in, const int* in_sizes, int n_in,
                              void* d_out, int out_size){
    const float* x      = (const float*)d_in[0];
    const float* latent = (const float*)d_in[1];
    const float* lift_w = (const float*)d_in[2];
    const float* lift_b = (const float*)d_in[3];
    const float* sc_w1  = (const float*)d_in[4];
    const float* sc_w2  = (const float*)d_in[5];
    const float* sc_w3  = (const float*)d_in[6];
    const float* sc_w4  = (const float*)d_in[7];
    const float* conv_w = (const float*)d_in[8];
    const float* conv_b = (const float*)d_in[9];
    const float* gn_g   = (const float*)d_in[10];
    const float* gn_b   = (const float*)d_in[11];
    const float* p1_w   = (const float*)d_in[12];
    const float* p1_b   = (const float*)d_in[13];
    const float* p2_w   = (const float*)d_in[14];
    const float* p2_b   = (const float*)d_in[15];
    const float* c1_w   = (const float*)d_in[16];
    const float* c1_b   = (const float*)d_in[17];
    const float* c2_w   = (const float*)d_in[18];
    const float* c2_b   = (const float*)d_in[19];
    float* out = (float*)d_out;

    static int smem_set = 0;
    if(!smem_set){
        cudaFuncSetAttribute(fwdWH_k, cudaFuncAttributeMaxDynamicSharedMemorySize, FWD_SMEM);
        smem_set = 1;
    }

    // Order keeps the ncu capture landing on fwdWH_k (4th launch).
    init_tables_k<<<6,256>>>();
    film1_k<<<128,256>>>(latent, c1_w, c1_b);
    lift_conv_k<<<2048,256>>>(x, lift_w, lift_b, conv_w, conv_b);

    const size_t WOFF = (size_t)64*64*12*12*12*2;
    for(int l=0;l<3;l++){
        fwdWH_k<<<dim3(32,64),256,FWD_SMEM>>>();
        if(l==0) film2_k<<<48,256>>>(c2_w, c2_b);
        fwdD_k<<<dim3(24,64),128>>>();
        mix_k<<<dim3(108,8),256>>>(sc_w1 + l*WOFF, sc_w2 + l*WOFF,
                                   sc_w3 + l*WOFF, sc_w4 + l*WOFF);
        invD_k<<<dim3(24,64),128>>>();
        invHW_gn_k<<<dim3(32,64),128>>>();
        gn_final_k<<<1,32>>>();
        if(l<2)
            gn_apply_conv_k<<<2048,256>>>(gn_g + l*64, gn_b + l*64, l,
                                          conv_w + (l+1)*4096, conv_b + (l+1)*64);
        else
            gn_apply_head_k<<<4096,256>>>(gn_g + l*64, gn_b + l*64, l,
                                          p1_w, p1_b, p2_w, p2_b, out);
    }
}

// round 17
// speedup vs baseline: 1.1111x; 1.0392x over previous
#include <cuda_runtime.h>
#include <math.h>

#define S3 262144        // 64^3
#define NMODE 6912       // 4 corners * 1728

// ---------------- scratch ----------------
__device__ float  g_v[64*S3];
__device__ float  g_s[64*S3];
__device__ float2 g_B[64*64*288];
__device__ float2 g_X[64*NMODE];   // corner-major: c*NMODE + corner*1728 + cmode
__device__ float2 g_Y[64*NMODE];
__device__ float  g_h1[1024];
__device__ float  g_film[384];
__device__ double g_gn[16];
__device__ float  g_gnf[16];
__device__ __align__(16) float2 tw_fWt[64*12];   // [w][kw]  fwd W twiddle (c,-s), transposed
__device__ __align__(16) float2 tw_iW[12*64];    // [kw][w]  inv W twiddle * alpha/64^3 (c,s)
__device__ __align__(16) float2 tw_fDHt[64*24];  // [x][j]   fwd D/H twiddle (c,-s), transposed
__device__ __align__(16) float2 tw_iDH[24*64];   // [j][x]   inv D/H twiddle (c,s)
__device__ __align__(16) float2 tw_fH13[64*14];  // [h][m]   fwd H bins 0..12 (c,-s), pad 14

__device__ __forceinline__ float gelu_f(float x){
    return 0.5f*x*(1.0f + erff(x*0.7071067811865476f));
}

#define CMAC(acc, a, t) { acc.x += a.x*t.x - a.y*t.y; acc.y += a.x*t.y + a.y*t.x; }

// ---------------- tables ----------------
__global__ void init_tables_k(){
    int t = blockIdx.x*blockDim.x + threadIdx.x;
    const double w0 = 6.283185307179586476925286766559/64.0;
    if(t < 768){
        int kw = t>>6, w = t&63;
        double s,c; sincos(w0*(double)(kw*w), &s, &c);
        tw_fWt[w*12+kw] = make_float2((float)c, (float)(-s));
        double al = (kw==0 ? 1.0 : 2.0) / 262144.0;
        tw_iW[kw*64+w] = make_float2((float)(al*c), (float)(al*s));
    }
    if(t < 1536){
        int j = t>>6, x = t&63;
        int bin = (j<12) ? j : (j+40);
        double s,c; sincos(w0*(double)(bin*x), &s, &c);
        tw_fDHt[x*24+j] = make_float2((float)c, (float)(-s));
        tw_iDH[j*64+x]  = make_float2((float)c, (float)( s));
    }
    if(t < 896){
        int h = t/14, m = t%14;
        if(m < 13){
            double s,c; sincos(w0*(double)(m*h), &s, &c);
            tw_fH13[t] = make_float2((float)c, (float)(-s));
        } else tw_fH13[t] = make_float2(0.f, 0.f);
    }
    if(t < 16) g_gn[t] = 0.0;
}

// ---------------- FiLM ----------------
__global__ void film1_k(const float* __restrict__ latent, const float* __restrict__ w,
                        const float* __restrict__ b){
    int wid  = (blockIdx.x*blockDim.x + threadIdx.x) >> 5;
    int lane = threadIdx.x & 31;
    if(wid >= 1024) return;
    const float* wr = w + wid*512;
    float acc = 0.f;
    for(int k=lane;k<512;k+=32) acc += latent[k]*wr[k];
    #pragma unroll
    for(int o=16;o;o>>=1) acc += __shfl_xor_sync(0xffffffffu, acc, o);
    if(lane==0) g_h1[wid] = gelu_f(acc + b[wid]);
}
__global__ void film2_k(const float* __restrict__ w, const float* __restrict__ b){
    int wid  = (blockIdx.x*blockDim.x + threadIdx.x) >> 5;
    int lane = threadIdx.x & 31;
    if(wid >= 384) return;
    const float* wr = w + wid*1024;
    float acc = 0.f;
    for(int k=lane;k<1024;k+=32) acc += g_h1[k]*wr[k];
    #pragma unroll
    for(int o=16;o;o>>=1) acc += __shfl_xor_sync(0xffffffffu, acc, o);
    if(lane==0) g_film[wid] = acc + b[wid];
}

// ---------------- lift + conv(layer0), register-tiled ----------------
__global__ void __launch_bounds__(256) lift_conv_k(const float* __restrict__ x,
        const float* __restrict__ lw, const float* __restrict__ lb,
        const float* __restrict__ cw, const float* __restrict__ cb){
    int s0 = blockIdx.x*128;
    __shared__ float vsh[64][128];
    __shared__ float wshT[64][68];
    int s = threadIdx.x & 127, chalf = threadIdx.x >> 7;
    float x0 = __ldg(&x[s0+s]),        x1 = __ldg(&x[S3+s0+s]);
    float x2 = __ldg(&x[2*S3+s0+s]),   x3 = __ldg(&x[3*S3+s0+s]);
    for(int i=threadIdx.x;i<4096;i+=256) wshT[i&63][i>>6] = cw[i];
    #pragma unroll
    for(int i=0;i<32;i++){
        int cc = i*2 + chalf;
        float v = __ldg(&lb[cc]) + __ldg(&lw[cc*4+0])*x0 + __ldg(&lw[cc*4+1])*x1
                                 + __ldg(&lw[cc*4+2])*x2 + __ldg(&lw[cc*4+3])*x3;
        vsh[cc][s] = v;
        g_v[(size_t)cc*S3 + s0 + s] = v;
    }
    __syncthreads();
    int o0 = (threadIdx.x>>5)*8, si = (threadIdx.x&31)*4;
    float acc[8][4];
    #pragma unroll
    for(int a=0;a<8;a++){ acc[a][0]=0.f;acc[a][1]=0.f;acc[a][2]=0.f;acc[a][3]=0.f; }
    for(int k=0;k<64;k++){
        float4 v4 = *(const float4*)&vsh[k][si];
        float4 wa = *(const float4*)&wshT[k][o0];
        float4 wb = *(const float4*)&wshT[k][o0+4];
        acc[0][0]+=wa.x*v4.x; acc[0][1]+=wa.x*v4.y; acc[0][2]+=wa.x*v4.z; acc[0][3]+=wa.x*v4.w;
        acc[1][0]+=wa.y*v4.x; acc[1][1]+=wa.y*v4.y; acc[1][2]+=wa.y*v4.z; acc[1][3]+=wa.y*v4.w;
        acc[2][0]+=wa.z*v4.x; acc[2][1]+=wa.z*v4.y; acc[2][2]+=wa.z*v4.z; acc[2][3]+=wa.z*v4.w;
        acc[3][0]+=wa.w*v4.x; acc[3][1]+=wa.w*v4.y; acc[3][2]+=wa.w*v4.z; acc[3][3]+=wa.w*v4.w;
        acc[4][0]+=wb.x*v4.x; acc[4][1]+=wb.x*v4.y; acc[4][2]+=wb.x*v4.z; acc[4][3]+=wb.x*v4.w;
        acc[5][0]+=wb.y*v4.x; acc[5][1]+=wb.y*v4.y; acc[5][2]+=wb.y*v4.z; acc[5][3]+=wb.y*v4.w;
        acc[6][0]+=wb.z*v4.x; acc[6][1]+=wb.z*v4.y; acc[6][2]+=wb.z*v4.z; acc[6][3]+=wb.z*v4.w;
        acc[7][0]+=wb.w*v4.x; acc[7][1]+=wb.w*v4.y; acc[7][2]+=wb.w*v4.z; acc[7][3]+=wb.w*v4.w;
    }
    #pragma unroll
    for(int oi=0;oi<8;oi++){
        float bb = __ldg(&cb[o0+oi]);
        *(float4*)&g_s[(size_t)(o0+oi)*S3 + s0 + si] =
            make_float4(acc[oi][0]+bb, acc[oi][1]+bb, acc[oi][2]+bb, acc[oi][3]+bb);
    }
}

// ---------------- fused forward DFT: H (real, 13 bins) then W ----------------
// 2 d-planes/block, 256 threads.
// smem floats: vsh 2*64*66=8448, A13 2*13*66 f2 = 3432 f, twWs 768 f2 = 1536 f
#define FWD_SMEM ((8448 + 3432 + 1536)*4)

template<int M0,int NB>
__device__ __forceinline__ void fwd_stage1(const float* base, float2* A13p, int wp2){
    float2 acc[NB][2];
    #pragma unroll
    for(int m=0;m<NB;m++){ acc[m][0]=make_float2(0.f,0.f); acc[m][1]=make_float2(0.f,0.f); }
    #pragma unroll 2
    for(int h=0;h<64;h++){
        float2 v2 = *(const float2*)(base + h*66 + wp2);
        #pragma unroll
        for(int m=0;m<NB;m++){
            float2 t = __ldg(&tw_fH13[h*14 + M0 + m]);
            acc[m][0].x += v2.x*t.x; acc[m][0].y += v2.x*t.y;
            acc[m][1].x += v2.y*t.x; acc[m][1].y += v2.y*t.y;
        }
    }
    #pragma unroll
    for(int m=0;m<NB;m++){
        A13p[(size_t)(M0+m)*66 + wp2]   = acc[m][0];
        A13p[(size_t)(M0+m)*66 + wp2+1] = acc[m][1];
    }
}

__global__ void __launch_bounds__(256) fwdWH_k(){
    extern __shared__ __align__(16) float sm[];
    float*  vsh  = sm;                        // [p][h][66]
    float2* A13  = (float2*)(sm + 8448);      // [p][13][66]
    float2* twWs = (float2*)(sm + 8448 + 3432); // [w][12]
    int d0 = blockIdx.x*2, c = blockIdx.y;

    for(int i=threadIdx.x;i<2048;i+=256){
        int p = i>>10, j = i&1023;
        float4 v4 = *(const float4*)(g_v + (size_t)(c*64+d0+p)*4096 + j*4);
        int h = j>>4, w4 = (j&15)*4;
        float* row = vsh + (size_t)(p*64+h)*66 + w4;
        row[0]=v4.x; row[1]=v4.y; row[2]=v4.z; row[3]=v4.w;
    }
    for(int i=threadIdx.x;i<768;i+=256) twWs[i] = tw_fWt[i];
    __syncthreads();

    // stage 1: H-DFT, real input, bins 0..12 only.
    // thread = (p, w-pair, bin-quarter {4,3,3,3})
    {
        int p = threadIdx.x>>7, u = threadIdx.x&127;
        int wp2 = (u&31)*2, q = u>>5;
        const float* base = vsh + (size_t)p*64*66;
        float2* A13p = A13 + (size_t)p*13*66;
        if(q==0)      fwd_stage1<0,4>(base, A13p, wp2);
        else if(q==1) fwd_stage1<4,3>(base, A13p, wp2);
        else if(q==2) fwd_stage1<7,3>(base, A13p, wp2);
        else          fwd_stage1<10,3>(base, A13p, wp2);
    }
    __syncthreads();

    // stage 2: W-DFT (contract w). thread (of 192) = (p, jh, kw-group of 3)
    if(threadIdx.x < 192){
        int idx = threadIdx.x;
        int p = idx/96, r2 = idx%96, jh = r2%24, kg = r2/24;
        int kw0 = kg*3;
        int bin = (jh<12) ? jh : 24-jh;
        float cs = (jh<12) ? 1.f : -1.f;
        const float2* arow = A13 + (size_t)(p*13+bin)*66;
        float2 b0={0,0}, b1={0,0}, b2={0,0};
        #pragma unroll 2
        for(int w=0;w<64;w++){
            float2 a  = arow[w];
            a.y *= cs;
            float2 t0 = twWs[w*12+kw0];
            float2 t1 = twWs[w*12+kw0+1];
            float2 t2 = twWs[w*12+kw0+2];
            CMAC(b0,a,t0); CMAC(b1,a,t1); CMAC(b2,a,t2);
        }
        float2* dst = g_B + (size_t)(c*64+d0+p)*288 + jh*12 + kw0;
        dst[0]=b0; dst[1]=b1; dst[2]=b2;
    }
}

// ---------------- forward DFT over D (stores corner-major) ----------------
__global__ void __launch_bounds__(128) fwdD_k(){
    int jh = blockIdx.x, c = blockIdx.y;
    __shared__ float2 Bsh[64][12];
    for(int i=threadIdx.x;i<768;i+=128){
        int d = i/12, kw = i - d*12;
        Bsh[d][kw] = g_B[(size_t)(c*64+d)*288 + jh*12 + kw];
    }
    __syncthreads();
    if(threadIdx.x < 96){
        int kw = threadIdx.x % 12, jd0 = (threadIdx.x/12)*3;
        float2 b0={0,0},b1={0,0},b2={0,0};
        for(int d=0;d<64;d++){
            float2 a = Bsh[d][kw];
            float2 t0 = __ldg(&tw_fDHt[d*24+jd0]);
            float2 t1 = __ldg(&tw_fDHt[d*24+jd0+1]);
            float2 t2 = __ldg(&tw_fDHt[d*24+jd0+2]);
            CMAC(b0,a,t0); CMAC(b1,a,t1); CMAC(b2,a,t2);
        }
        int jhm = jh % 12, cbase = (jh>=12) ? 2 : 0;
        #pragma unroll
        for(int r=0;r<3;r++){
            int jd = jd0 + r;
            int corner = cbase + (jd>=12 ? 1 : 0);
            int cmode = ((jd%12)*12 + jhm)*12 + kw;
            float2 b = (r==0)?b0:(r==1)?b1:b2;
            g_X[(size_t)c*NMODE + corner*1728 + cmode] = b;
        }
    }
}

// ---------------- per-mode channel mix: float4 streaming ----------------
__global__ void __launch_bounds__(256) mix_k(const float* __restrict__ w1, const float* __restrict__ w2,
                                             const float* __restrict__ w3, const float* __restrict__ w4){
    int corner = blockIdx.x / 27;
    int c0 = (blockIdx.x - corner*27) * 64;
    const float* wbase = (corner==0)?w1:(corner==1)?w2:(corner==2)?w3:w4;
    __shared__ float2 xs[64][64];
    int tx = threadIdx.x & 31, ty = threadIdx.x >> 5;
    for(int i=ty; i<64; i+=8)
        ((float4*)xs[i])[tx] = *(const float4*)(&g_X[(size_t)i*NMODE + corner*1728 + c0 + tx*2]);
    __syncthreads();
    int o = blockIdx.y*8 + ty;
    const float* Wp = wbase + ((size_t)o*1728 + c0 + tx*2)*2;
    float re0=0.f,im0=0.f,re1=0.f,im1=0.f;
    #pragma unroll 8
    for(int i=0;i<64;i++){
        float4 wv = *(const float4*)(Wp + (size_t)i*221184);
        float4 xx = ((const float4*)xs[i])[tx];
        re0 += xx.x*wv.x - xx.y*wv.y; im0 += xx.x*wv.y + xx.y*wv.x;
        re1 += xx.z*wv.z - xx.w*wv.w; im1 += xx.z*wv.w + xx.w*wv.z;
    }
    *(float4*)(&g_Y[(size_t)o*NMODE + corner*1728 + c0 + tx*2]) = make_float4(re0,im0,re1,im1);
}

// ---------------- inverse DFT over D (conjugate-pair halved) ----------------
__global__ void __launch_bounds__(128) invD_k(){
    int jh = blockIdx.x, c = blockIdx.y;
    __shared__ __align__(16) float2 Ysh[24][12];
    __shared__ __align__(16) float2 Ssh[11][12];
    __shared__ __align__(16) float2 Dsh[11][12];
    int jhm = jh % 12, cbase = (jh>=12) ? 2 : 0;
    for(int i=threadIdx.x;i<288;i+=128){
        int jd = i/12, kw = i - jd*12;
        int corner = cbase + (jd>=12 ? 1 : 0);
        int cmode = ((jd%12)*12 + jhm)*12 + kw;
        Ysh[jd][kw] = g_Y[(size_t)c*NMODE + corner*1728 + cmode];
    }
    __syncthreads();
    for(int i=threadIdx.x;i<132;i+=128){
        int m = i/12, kw = i%12;          // pair: bins (m+1, -(m+1)) = jd (m+1, 23-m)
        float2 ya = Ysh[m+1][kw], yb = Ysh[23-m][kw];
        Ssh[m][kw] = make_float2(ya.x+yb.x, ya.y+yb.y);
        Dsh[m][kw] = make_float2(ya.x-yb.x, ya.y-yb.y);
    }
    __syncthreads();
    int d = threadIdx.x & 63, kw0 = (threadIdx.x>>6)*6;
    float2 acc[6];
    // bin 0: twiddle (1,0)
    {
        const float4* y0 = (const float4*)&Ysh[0][kw0];
        float4 a = y0[0], b = y0[1], e = y0[2];
        acc[0]=make_float2(a.x,a.y); acc[1]=make_float2(a.z,a.w);
        acc[2]=make_float2(b.x,b.y); acc[3]=make_float2(b.z,b.w);
        acc[4]=make_float2(e.x,e.y); acc[5]=make_float2(e.z,e.w);
    }
    // bin -12 (jd=12): standard CMAC
    {
        float2 t = __ldg(&tw_iDH[12*64+d]);
        const float4* yp = (const float4*)&Ysh[12][kw0];
        float4 y0 = yp[0], y1 = yp[1], y2 = yp[2];
        float2 v;
        v=make_float2(y0.x,y0.y); CMAC(acc[0],v,t);
        v=make_float2(y0.z,y0.w); CMAC(acc[1],v,t);
        v=make_float2(y1.x,y1.y); CMAC(acc[2],v,t);
        v=make_float2(y1.z,y1.w); CMAC(acc[3],v,t);
        v=make_float2(y2.x,y2.y); CMAC(acc[4],v,t);
        v=make_float2(y2.z,y2.w); CMAC(acc[5],v,t);
    }
    #pragma unroll 2
    for(int m=0;m<11;m++){
        float2 t = __ldg(&tw_iDH[(m+1)*64+d]);
        const float4* sp = (const float4*)&Ssh[m][kw0];
        const float4* dp = (const float4*)&Dsh[m][kw0];
        float4 s0=sp[0], s1=sp[1], s2=sp[2];
        float4 d0=dp[0], d1=dp[1], d2=dp[2];
        acc[0].x += s0.x*t.x - d0.y*t.y;  acc[0].y += s0.y*t.x + d0.x*t.y;
        acc[1].x += s0.z*t.x - d0.w*t.y;  acc[1].y += s0.w*t.x + d0.z*t.y;
        acc[2].x += s1.x*t.x - d1.y*t.y;  acc[2].y += s1.y*t.x + d1.x*t.y;
        acc[3].x += s1.z*t.x - d1.w*t.y;  acc[3].y += s1.w*t.x + d1.z*t.y;
        acc[4].x += s2.x*t.x - d2.y*t.y;  acc[4].y += s2.y*t.x + d2.x*t.y;
        acc[5].x += s2.z*t.x - d2.w*t.y;  acc[5].y += s2.w*t.x + d2.z*t.y;
    }
    float2* dst = g_B + (size_t)(c*64+d)*288 + jh*12 + kw0;
    dst[0]=acc[0]; dst[1]=acc[1]; dst[2]=acc[2];
    dst[3]=acc[3]; dst[4]=acc[4]; dst[5]=acc[5];
}

// ---------------- fused inverse H + W + residual add + GN stats ----------------
// 2 d-planes per block, 128 threads. Stage A uses conjugate-pair halving.
__global__ void __launch_bounds__(128) invHW_gn_k(){
    int d0 = blockIdx.x*2, c = blockIdx.y;
    __shared__ __align__(16) float2 Bsh[2][288];
    __shared__ __align__(16) float2 Ssh[2][11][12];
    __shared__ __align__(16) float2 Dsh[2][11][12];
    __shared__ __align__(16) float Ash[2][64][26];
    __shared__ __align__(16) float T2[24][68];
    __shared__ float redS[4], redQ[4];

    for(int i=threadIdx.x;i<576;i+=128){
        int p = (i>=288) ? 1 : 0;
        int idx = i - p*288;
        Bsh[p][idx] = g_B[(size_t)(c*64+d0+p)*288 + idx];
    }
    for(int i=threadIdx.x;i<1536;i+=128){
        int k = i>>6, w = i&63;
        float2 t = tw_iW[(k>>1)*64 + w];
        T2[k][w] = (k&1) ? -t.y : t.x;
    }
    __syncthreads();
    for(int i=threadIdx.x;i<264;i+=128){
        int p = i/132, r = i%132, m = r/12, kw = r%12;
        float2 ba = Bsh[p][(m+1)*12+kw], bb = Bsh[p][(23-m)*12+kw];
        Ssh[p][m][kw] = make_float2(ba.x+bb.x, ba.y+bb.y);
        Dsh[p][m][kw] = make_float2(ba.x-bb.x, ba.y-bb.y);
    }
    __syncthreads();

    // stage A: inverse H. thread = (plane, 2h, 6kw) with pair-halving.
    {
        int p = threadIdx.x>>6, u = threadIdx.x&63;
        int h0 = (u&31)*2, kw0 = (u>>5)*6;
        float are[2][6], aim[2][6];
        // bin 0: twiddle (1,0)
        {
            const float4* bp = (const float4*)&Bsh[p][kw0];
            float4 b0 = bp[0], b1 = bp[1], b2 = bp[2];
            float br[6] = {b0.x,b0.z,b1.x,b1.z,b2.x,b2.z};
            float bi[6] = {b0.y,b0.w,b1.y,b1.w,b2.y,b2.w};
            #pragma unroll
            for(int j=0;j<6;j++){
                are[0][j]=br[j]; aim[0][j]=bi[j];
                are[1][j]=br[j]; aim[1][j]=bi[j];
            }
        }
        // bin -12 (jh=12): standard CMAC for both h
        {
            float4 tt = __ldg((const float4*)&tw_iDH[12*64+h0]);
            const float4* bp = (const float4*)&Bsh[p][144+kw0];
            float4 b0 = bp[0], b1 = bp[1], b2 = bp[2];
            float br[6] = {b0.x,b0.z,b1.x,b1.z,b2.x,b2.z};
            float bi[6] = {b0.y,b0.w,b1.y,b1.w,b2.y,b2.w};
            #pragma unroll
            for(int j=0;j<6;j++){
                are[0][j] += br[j]*tt.x - bi[j]*tt.y;
                aim[0][j] += br[j]*tt.y + bi[j]*tt.x;
                are[1][j] += br[j]*tt.z - bi[j]*tt.w;
                aim[1][j] += br[j]*tt.w + bi[j]*tt.z;
            }
        }
        #pragma unroll 2
        for(int m=0;m<11;m++){
            float4 tt = __ldg((const float4*)&tw_iDH[(m+1)*64+h0]);   // c0,s0,c1,s1
            const float4* sp = (const float4*)&Ssh[p][m][kw0];
            const float4* dp = (const float4*)&Dsh[p][m][kw0];
            float4 s0=sp[0], s1=sp[1], s2=sp[2];
            float4 dd0=dp[0], dd1=dp[1], dd2=dp[2];
            float sr[6]={s0.x,s0.z,s1.x,s1.z,s2.x,s2.z};
            float si[6]={s0.y,s0.w,s1.y,s1.w,s2.y,s2.w};
            float dr[6]={dd0.x,dd0.z,dd1.x,dd1.z,dd2.x,dd2.z};
            float di[6]={dd0.y,dd0.w,dd1.y,dd1.w,dd2.y,dd2.w};
            #pragma unroll
            for(int j=0;j<6;j++){
                are[0][j] += sr[j]*tt.x - di[j]*tt.y;
                aim[0][j] += si[j]*tt.x + dr[j]*tt.y;
                are[1][j] += sr[j]*tt.z - di[j]*tt.w;
                aim[1][j] += si[j]*tt.z + dr[j]*tt.w;
            }
        }
        #pragma unroll
        for(int i=0;i<2;i++)
            #pragma unroll
            for(int j=0;j<6;j++){
                float* a = &Ash[p][h0+i][2*(kw0+j)];
                a[0]=are[i][j]; a[1]=aim[i][j];
            }
    }
    __syncthreads();

    // stage B: inverse W as real GEMM (K=24) + residual + GN stats
    int wg = threadIdx.x&7, hg = threadIdx.x>>3;
    float ssum=0.f, sq=0.f;
    for(int p=0;p<2;p++){
        float acc[4][8];
        #pragma unroll
        for(int i=0;i<4;i++)
            #pragma unroll
            for(int j=0;j<8;j++) acc[i][j]=0.f;
        for(int k=0;k<24;k++){
            float4 Tw0 = *(const float4*)&T2[k][wg*8];
            float4 Tw1 = *(const float4*)&T2[k][wg*8+4];
            float a0 = Ash[p][hg*4+0][k];
            float a1 = Ash[p][hg*4+1][k];
            float a2 = Ash[p][hg*4+2][k];
            float a3 = Ash[p][hg*4+3][k];
            acc[0][0]+=a0*Tw0.x; acc[0][1]+=a0*Tw0.y; acc[0][2]+=a0*Tw0.z; acc[0][3]+=a0*Tw0.w;
            acc[0][4]+=a0*Tw1.x; acc[0][5]+=a0*Tw1.y; acc[0][6]+=a0*Tw1.z; acc[0][7]+=a0*Tw1.w;
            acc[1][0]+=a1*Tw0.x; acc[1][1]+=a1*Tw0.y; acc[1][2]+=a1*Tw0.z; acc[1][3]+=a1*Tw0.w;
            acc[1][4]+=a1*Tw1.x; acc[1][5]+=a1*Tw1.y; acc[1][6]+=a1*Tw1.z; acc[1][7]+=a1*Tw1.w;
            acc[2][0]+=a2*Tw0.x; acc[2][1]+=a2*Tw0.y; acc[2][2]+=a2*Tw0.z; acc[2][3]+=a2*Tw0.w;
            acc[2][4]+=a2*Tw1.x; acc[2][5]+=a2*Tw1.y; acc[2][6]+=a2*Tw1.z; acc[2][7]+=a2*Tw1.w;
            acc[3][0]+=a3*Tw0.x; acc[3][1]+=a3*Tw0.y; acc[3][2]+=a3*Tw0.z; acc[3][3]+=a3*Tw0.w;
            acc[3][4]+=a3*Tw1.x; acc[3][5]+=a3*Tw1.y; acc[3][6]+=a3*Tw1.z; acc[3][7]+=a3*Tw1.w;
        }
        float* srow = g_s + (size_t)c*S3 + (size_t)(d0+p)*4096;
        #pragma unroll
        for(int i=0;i<4;i++){
            int h = hg*4+i;
            float4* q = (float4*)(srow + h*64 + wg*8);
            float4 s0 = q[0], s1 = q[1];
            s0.x+=acc[i][0]; s0.y+=acc[i][1]; s0.z+=acc[i][2]; s0.w+=acc[i][3];
            s1.x+=acc[i][4]; s1.y+=acc[i][5]; s1.z+=acc[i][6]; s1.w+=acc[i][7];
            q[0]=s0; q[1]=s1;
            ssum += s0.x+s0.y+s0.z+s0.w + s1.x+s1.y+s1.z+s1.w;
            sq   += s0.x*s0.x+s0.y*s0.y+s0.z*s0.z+s0.w*s0.w
                  + s1.x*s1.x+s1.y*s1.y+s1.z*s1.z+s1.w*s1.w;
        }
    }
    #pragma unroll
    for(int o=16;o;o>>=1){ ssum += __shfl_xor_sync(0xffffffffu,ssum,o);
                           sq   += __shfl_xor_sync(0xffffffffu,sq,o); }
    int wp = threadIdx.x & 31, warp = threadIdx.x >> 5;
    if(wp==0){ redS[warp]=ssum; redQ[warp]=sq; }
    __syncthreads();
    if(threadIdx.x==0){
        float S = redS[0]+redS[1]+redS[2]+redS[3];
        float Q = redQ[0]+redQ[1]+redQ[2]+redQ[3];
        int g = c>>3;
        atomicAdd(&g_gn[g*2],   (double)S);
        atomicAdd(&g_gn[g*2+1], (double)Q);
    }
}

__global__ void gn_final_k(){
    int g = threadIdx.x;
    float mu_f=0.f, rs_f=0.f;
    if(g<8){
        double n = 8.0*(double)S3;
        double mu = g_gn[g*2]/n;
        double var = g_gn[g*2+1]/n - mu*mu;
        mu_f = (float)mu; rs_f = (float)(1.0/sqrt(var + 1e-5));
    }
    __syncthreads();
    if(g<8){ g_gnf[g*2]=mu_f; g_gnf[g*2+1]=rs_f; }
    if(g<16) g_gn[g]=0.0;
}

// ---------------- GN-apply + GELU + FiLM + conv(next layer) ----------------
__global__ void __launch_bounds__(256) gn_apply_conv_k(const float* __restrict__ gg, const float* __restrict__ gb,
        int l, const float* __restrict__ cw, const float* __restrict__ cb){
    int s0 = blockIdx.x*128;
    __shared__ float vsh[64][128];
    __shared__ float wshT[64][68];
    int s = threadIdx.x & 127, chalf = threadIdx.x >> 7;
    for(int i=threadIdx.x;i<4096;i+=256) wshT[i&63][i>>6] = cw[i];
    #pragma unroll
    for(int i=0;i<32;i++){
        int cc = i*2 + chalf;
        int g = cc>>3;
        float xv = (g_s[(size_t)cc*S3+s0+s]-g_gnf[g*2])*g_gnf[g*2+1]*__ldg(&gg[cc]) + __ldg(&gb[cc]);
        float y = gelu_f(xv);
        float v = y*(1.f+g_film[(l*64+cc)*2]) + g_film[(l*64+cc)*2+1];
        vsh[cc][s] = v;
        g_v[(size_t)cc*S3+s0+s] = v;
    }
    __syncthreads();
    int o0 = (threadIdx.x>>5)*8, si = (threadIdx.x&31)*4;
    float acc[8][4];
    #pragma unroll
    for(int a=0;a<8;a++){ acc[a][0]=0.f;acc[a][1]=0.f;acc[a][2]=0.f;acc[a][3]=0.f; }
    for(int k=0;k<64;k++){
        float4 v4 = *(const float4*)&vsh[k][si];
        float4 wa = *(const float4*)&wshT[k][o0];
        float4 wb = *(const float4*)&wshT[k][o0+4];
        acc[0][0]+=wa.x*v4.x; acc[0][1]+=wa.x*v4.y; acc[0][2]+=wa.x*v4.z; acc[0][3]+=wa.x*v4.w;
        acc[1][0]+=wa.y*v4.x; acc[1][1]+=wa.y*v4.y; acc[1][2]+=wa.y*v4.z; acc[1][3]+=wa.y*v4.w;
        acc[2][0]+=wa.z*v4.x; acc[2][1]+=wa.z*v4.y; acc[2][2]+=wa.z*v4.z; acc[2][3]+=wa.z*v4.w;
        acc[3][0]+=wa.w*v4.x; acc[3][1]+=wa.w*v4.y; acc[3][2]+=wa.w*v4.z; acc[3][3]+=wa.w*v4.w;
        acc[4][0]+=wb.x*v4.x; acc[4][1]+=wb.x*v4.y; acc[4][2]+=wb.x*v4.z; acc[4][3]+=wb.x*v4.w;
        acc[5][0]+=wb.y*v4.x; acc[5][1]+=wb.y*v4.y; acc[5][2]+=wb.y*v4.z; acc[5][3]+=wb.y*v4.w;
        acc[6][0]+=wb.z*v4.x; acc[6][1]+=wb.z*v4.y; acc[6][2]+=wb.z*v4.z; acc[6][3]+=wb.z*v4.w;
        acc[7][0]+=wb.w*v4.x; acc[7][1]+=wb.w*v4.y; acc[7][2]+=wb.w*v4.z; acc[7][3]+=wb.w*v4.w;
    }
    #pragma unroll
    for(int oi=0;oi<8;oi++){
        float bb = __ldg(&cb[o0+oi]);
        *(float4*)&g_s[(size_t)(o0+oi)*S3 + s0 + si] =
            make_float4(acc[oi][0]+bb, acc[oi][1]+bb, acc[oi][2]+bb, acc[oi][3]+bb);
    }
}

// ---------------- last layer: GN-apply + FiLM + p1 + GELU + p2 ----------------
__global__ void __launch_bounds__(256) gn_apply_head_k(const float* __restrict__ gg, const float* __restrict__ gb,
        int l, const float* __restrict__ w1, const float* __restrict__ b1,
        const float* __restrict__ w2, const float* __restrict__ b2, float* __restrict__ out){
    int s0 = blockIdx.x*64;
    __shared__ float vsh[64][64];
    __shared__ float wshT[64][68];
    __shared__ float w2s[3][128];
    __shared__ float red[16][3][64];
    int s = threadIdx.x & 63, cq = threadIdx.x >> 6;
    for(int i=threadIdx.x;i<384;i+=256){ int j=i>>7, o=i&127; w2s[j][o]=w2[j*128+o]; }
    #pragma unroll
    for(int i=0;i<16;i++){
        int cc = i*4 + cq;
        int g = cc>>3;
        float xv = (g_s[(size_t)cc*S3+s0+s]-g_gnf[g*2])*g_gnf[g*2+1]*__ldg(&gg[cc]) + __ldg(&gb[cc]);
        float y = gelu_f(xv);
        vsh[cc][s] = y*(1.f+g_film[(l*64+cc)*2]) + g_film[(l*64+cc)*2+1];
    }
    int og = threadIdx.x >> 4, sg = threadIdx.x & 15;
    int o0 = og*4, si = sg*4;
    float p[3][4];
    #pragma unroll
    for(int j=0;j<3;j++){ p[j][0]=0.f;p[j][1]=0.f;p[j][2]=0.f;p[j][3]=0.f; }
    for(int half=0; half<2; half++){
        __syncthreads();
        for(int i=threadIdx.x;i<4096;i+=256){ int o=i>>6,k=i&63; wshT[k][o]=w1[(half*64+o)*64+k]; }
        __syncthreads();
        float acc[4][4];
        #pragma unroll
        for(int a=0;a<4;a++){ acc[a][0]=0.f;acc[a][1]=0.f;acc[a][2]=0.f;acc[a][3]=0.f; }
        for(int k=0;k<64;k++){
            float4 v4 = *(const float4*)&vsh[k][si];
            float4 wv = *(const float4*)&wshT[k][o0];
            acc[0][0]+=wv.x*v4.x; acc[0][1]+=wv.x*v4.y; acc[0][2]+=wv.x*v4.z; acc[0][3]+=wv.x*v4.w;
            acc[1][0]+=wv.y*v4.x; acc[1][1]+=wv.y*v4.y; acc[1][2]+=wv.y*v4.z; acc[1][3]+=wv.y*v4.w;
            acc[2][0]+=wv.z*v4.x; acc[2][1]+=wv.z*v4.y; acc[2][2]+=wv.z*v4.z; acc[2][3]+=wv.z*v4.w;
            acc[3][0]+=wv.w*v4.x; acc[3][1]+=wv.w*v4.y; acc[3][2]+=wv.w*v4.z; acc[3][3]+=wv.w*v4.w;
        }
        #pragma unroll
        for(int oi=0;oi<4;oi++){
            int o = half*64 + o0 + oi;
            float bb = __ldg(&b1[o]);
            #pragma unroll
            for(int sx=0;sx<4;sx++){
                float u = gelu_f(acc[oi][sx] + bb);
                p[0][sx] += u*w2s[0][o];
                p[1][sx] += u*w2s[1][o];
                p[2][sx] += u*w2s[2][o];
            }
        }
    }
    #pragma unroll
    for(int j=0;j<3;j++){
        red[og][j][si+0]=p[j][0]; red[og][j][si+1]=p[j][1];
        red[og][j][si+2]=p[j][2]; red[og][j][si+3]=p[j][3];
    }
    __syncthreads();
    if(threadIdx.x < 64){
        int ss = threadIdx.x;
        #pragma unroll
        for(int j=0;j<3;j++){
            float acc = __ldg(&b2[j]);
            #pragma unroll
            for(int gq=0;gq<16;gq++) acc += red[gq][j][ss];
            out[(size_t)j*S3 + s0 + ss] = acc;
        }
    }
}

// ---------------- launch ----------------
extern "C" void kernel_launch(void* const* d_in, const int* in_sizes, int n_in,
                              void* d_out, int out_size){
    const float* x      = (const float*)d_in[0];
    const float* latent = (const float*)d_in[1];
    const float* lift_w = (const float*)d_in[2];
    const float* lift_b = (const float*)d_in[3];
    const float* sc_w1  = (const float*)d_in[4];
    const float* sc_w2  = (const float*)d_in[5];
    const float* sc_w3  = (const float*)d_in[6];
    const float* sc_w4  = (const float*)d_in[7];
    const float* conv_w = (const float*)d_in[8];
    const float* conv_b = (const float*)d_in[9];
    const float* gn_g   = (const float*)d_in[10];
    const float* gn_b   = (const float*)d_in[11];
    const float* p1_w   = (const float*)d_in[12];
    const float* p1_b   = (const float*)d_in[13];
    const float* p2_w   = (const float*)d_in[14];
    const float* p2_b   = (const float*)d_in[15];
    const float* c1_w   = (const float*)d_in[16];
    const float* c1_b   = (const float*)d_in[17];
    const float* c2_w   = (const float*)d_in[18];
    const float* c2_b   = (const float*)d_in[19];
    float* out = (float*)d_out;

    static int smem_set = 0;
    if(!smem_set){
        cudaFuncSetAttribute(fwdWH_k, cudaFuncAttributeMaxDynamicSharedMemorySize, FWD_SMEM);
        smem_set = 1;
    }

    // Order keeps the ncu capture landing on fwdWH_k (4th launch).
    init_tables_k<<<6,256>>>();
    film1_k<<<128,256>>>(latent, c1_w, c1_b);
    lift_conv_k<<<2048,256>>>(x, lift_w, lift_b, conv_w, conv_b);

    const size_t WOFF = (size_t)64*64*12*12*12*2;
    for(int l=0;l<3;l++){
        fwdWH_k<<<dim3(32,64),256,FWD_SMEM>>>();
        if(l==0) film2_k<<<48,256>>>(c2_w, c2_b);
        fwdD_k<<<dim3(24,64),128>>>();
        mix_k<<<dim3(108,8),256>>>(sc_w1 + l*WOFF, sc_w2 + l*WOFF,
                                   sc_w3 + l*WOFF, sc_w4 + l*WOFF);
        invD_k<<<dim3(24,64),128>>>();
        invHW_gn_k<<<dim3(32,64),128>>>();
        gn_final_k<<<1,32>>>();
        if(l<2)
            gn_apply_conv_k<<<2048,256>>>(gn_g + l*64, gn_b + l*64, l,
                                          conv_w + (l+1)*4096, conv_b + (l+1)*64);
        else
            gn_apply_head_k<<<4096,256>>>(gn_g + l*64, gn_b + l*64, l,
                                          p1_w, p1_b, p2_w, p2_b, out);
    }
}